// round 8
// baseline (speedup 1.0000x reference)
#include <cuda_runtime.h>
#include <math.h>

// Problem dims
#define NB 1024   // batch
#define NT 64     // time steps
#define NV 1024   // vocab
#define NE 512    // embed dim
#define NM 1024   // modes
#define NL 32     // MZI layers
#define NPE 512   // even pairs
#define NPO 511   // odd pairs
#define G3E 1536  // 3*NE

// Scratch (no allocations allowed -> __device__ globals)
__device__ float g_G[NV * G3E];       // token gate table: embed@W_ih^T + b_ih
__device__ float g_h[2][NB * NE];     // GRU hidden double buffer
__device__ float g_zc[NB * 2 * NM];   // h@Wc^T + bc
__device__ float g_pr[NB * NM];       // psi real
__device__ float g_pi[NB * NM];       // psi imag
__device__ unsigned g_barCount;       // grid barrier state
__device__ unsigned g_barGen;

// ---------------------------------------------------------------------------
// tf32 helpers
// ---------------------------------------------------------------------------
__device__ __forceinline__ float to_tf32(float x) {
    unsigned u;
    asm("cvt.rna.tf32.f32 %0, %1;" : "=r"(u) : "f"(x));
    return __uint_as_float(u);
}

__device__ __forceinline__ void mma_tf32(float* c, const unsigned* a, const unsigned* b) {
    asm("mma.sync.aligned.m16n8k8.row.col.f32.tf32.tf32.f32 "
        "{%0,%1,%2,%3}, {%4,%5,%6,%7}, {%8,%9}, {%0,%1,%2,%3};"
        : "+f"(c[0]), "+f"(c[1]), "+f"(c[2]), "+f"(c[3])
        : "r"(a[0]), "r"(a[1]), "r"(a[2]), "r"(a[3]), "r"(b[0]), "r"(b[1]));
}

// ---------------------------------------------------------------------------
// Grid-wide spin barrier (all 128 CTAs wave-1 resident: 1 CTA/SM via smem).
// ---------------------------------------------------------------------------
#define NCTA 128
__device__ __forceinline__ void grid_sync()
{
    __threadfence();
    __syncthreads();
    if (threadIdx.x == 0) {
        unsigned gen = *(volatile unsigned*)&g_barGen;
        if (atomicAdd(&g_barCount, 1u) == NCTA - 1) {
            g_barCount = 0;
            __threadfence();
            atomicExch(&g_barGen, gen + 1u);
        } else {
            while (*(volatile unsigned*)&g_barGen == gen) { __nanosleep(64); }
            __threadfence();
        }
    }
    __syncthreads();
}

// ---------------------------------------------------------------------------
// Persistent GRU, fragment-permuted SMEM operands.
//
// Each CTA: 128 batch rows x 32 hidden units (96 gate cols, gates interleaved
// e*3+g). W slice lives in SMEM for all 64 steps, stored in B-fragment order:
//   Wp[((n8*64 + k8)*32 + 4*g + tq)*2 + br]  = W[n=8*n8+g][k=8*k8+tq+4*br]
// -> per n8 x k8 frag: one LDS.64 per lane (b0,b1), conflict-free.
// A (h) staged per 16-k tile in A-fragment order:
//   Ap[((m16*2+ks)*32 + 4*g + tq)*4 + r]
//     = A[row=16*m16+g+8*(r&1)][col=8*ks+tq+4*(r>>1)]
// -> per m16 x ks frag: one LDS.128 per lane (a0..a3), conflict-free.
// NOTE store stride per tq step is 4 floats (the *4 wraps the tq term).
// Warp grid 4m x 2n, warp tile 32x48 (m16n8k8 tf32).
// ---------------------------------------------------------------------------
#define WS_FLOATS (96 * 512)            // 49152 floats = 196608 B
#define AS_STAGE  2048                  // one 128x16 tile in frag order
#define SMEM_FLOATS (WS_FLOATS + 2 * AS_STAGE)
#define SMEM_BYTES (SMEM_FLOATS * 4)    // 212,992 B

__global__ __launch_bounds__(256, 1) void gru_persist(
    float* __restrict__ h0, float* __restrict__ h1,
    const float* __restrict__ W_hh, const float* __restrict__ b_hh,
    const int* __restrict__ tokens)
{
    extern __shared__ float smem[];
    float* Ws = smem;                    // frag-ordered W slice
    float* As = smem + WS_FLOATS;        // [2][2048]
    float* Cs = As;                      // epilogue staging reuses A space

    int tid = threadIdx.x;
    int lane = tid & 31, w = tid >> 5;
    int g = lane >> 2, tq = lane & 3;
    int m0w = (w >> 1);                  // warp m16-pair index (0..3)
    int n0 = (w & 1) * 48;               // warp col base (0 or 48)
    int n8base = (w & 1) * 6;
    int rb = blockIdx.y * 128;           // global row base
    int ecb = blockIdx.x * 32;           // global e base
    int cb = ecb * 3;                    // global gate-col base

    // ---- one-time: build frag-ordered, gate-interleaved, tf32 W slice ----
    for (int idx = tid; idx < 96 * 512; idx += 256) {
        int nl = idx >> 9;               // 0..95
        int k = idx & 511;
        int col = cb + nl;               // interleaved gate col
        int e = col / 3, gg = col - 3 * e;
        float v = to_tf32(W_hh[(size_t)(gg * NE + e) * NE + k]);
        int n8 = nl >> 3, bg = nl & 7;
        int k8 = k >> 3, btq = k & 3, br = (k >> 2) & 1;
        Ws[((n8 * 64 + k8) * 32 + 4 * bg + btq) * 2 + br] = v;
    }
    __syncthreads();

    // A loader mapping: each thread handles rows (tid>>2) and 64+(tid>>2),
    // q = tid&3 selects the 4-col group within the 16-wide k-tile.
    int aRow0 = tid >> 2, aRow1 = 64 + (tid >> 2), aQ = tid & 3;
    int aKs = aQ >> 1, aHalf = aQ & 1;
    // scatter bases (float index); consecutive loaded cols advance tq -> +4
    int r0m16 = aRow0 >> 4, r0g = aRow0 & 7, r0hi = (aRow0 >> 3) & 1;
    int r1m16 = aRow1 >> 4, r1g = aRow1 & 7, r1hi = (aRow1 >> 3) & 1;
    int aOff0 = ((r0m16 * 2 + aKs) * 32 + 4 * r0g) * 4 + r0hi + 2 * aHalf;
    int aOff1 = ((r1m16 * 2 + aKs) * 32 + 4 * r1g) * 4 + r1hi + 2 * aHalf;

    for (int t = 0; t < NT; t++) {
        const float* hin = (t & 1) ? h1 : h0;
        float* hout      = (t & 1) ? h0 : h1;
        const float* Ag = hin + (size_t)rb * NE;

        // preload k-tile 0 into stage 0
        {
            float4 a0 = *(const float4*)(Ag + (size_t)aRow0 * NE + aQ * 4);
            float4 a1 = *(const float4*)(Ag + (size_t)aRow1 * NE + aQ * 4);
            float* d0 = As + aOff0;
            d0[0]  = to_tf32(a0.x); d0[4]  = to_tf32(a0.y);
            d0[8]  = to_tf32(a0.z); d0[12] = to_tf32(a0.w);
            float* d1 = As + aOff1;
            d1[0]  = to_tf32(a1.x); d1[4]  = to_tf32(a1.y);
            d1[8]  = to_tf32(a1.z); d1[12] = to_tf32(a1.w);
        }
        __syncthreads();

        float acc[2][6][4];
#pragma unroll
        for (int mi = 0; mi < 2; mi++)
#pragma unroll
            for (int ni = 0; ni < 6; ni++)
#pragma unroll
                for (int j = 0; j < 4; j++) acc[mi][ni][j] = 0.f;

        for (int kt = 0; kt < 32; kt++) {
            const float* Acur = As + (kt & 1) * AS_STAGE;
            float4 na0, na1;
            if (kt < 31) {
                int k0 = (kt + 1) * 16;
                na0 = *(const float4*)(Ag + (size_t)aRow0 * NE + k0 + aQ * 4);
                na1 = *(const float4*)(Ag + (size_t)aRow1 * NE + k0 + aQ * 4);
            }
#pragma unroll
            for (int ks = 0; ks < 2; ks++) {
                int k8 = kt * 2 + ks;
                // A frags: one LDS.128 per mi
                float4 av0 = *(const float4*)(Acur + (((m0w * 2 + 0) * 2 + ks) * 32 + lane) * 4);
                float4 av1 = *(const float4*)(Acur + (((m0w * 2 + 1) * 2 + ks) * 32 + lane) * 4);
                unsigned af0[4] = { __float_as_uint(av0.x), __float_as_uint(av0.y),
                                    __float_as_uint(av0.z), __float_as_uint(av0.w) };
                unsigned af1[4] = { __float_as_uint(av1.x), __float_as_uint(av1.y),
                                    __float_as_uint(av1.z), __float_as_uint(av1.w) };
#pragma unroll
                for (int ni = 0; ni < 6; ni++) {
                    float2 bv = *(const float2*)(Ws + (((n8base + ni) * 64 + k8) * 32 + lane) * 2);
                    unsigned bf[2] = { __float_as_uint(bv.x), __float_as_uint(bv.y) };
                    mma_tf32(acc[0][ni], af0, bf);
                    mma_tf32(acc[1][ni], af1, bf);
                }
            }
            if (kt < 31) {
                float* d0 = As + ((kt + 1) & 1) * AS_STAGE + aOff0;
                d0[0]  = to_tf32(na0.x); d0[4]  = to_tf32(na0.y);
                d0[8]  = to_tf32(na0.z); d0[12] = to_tf32(na0.w);
                float* d1 = As + ((kt + 1) & 1) * AS_STAGE + aOff1;
                d1[0]  = to_tf32(na1.x); d1[4]  = to_tf32(na1.y);
                d1[8]  = to_tf32(na1.z); d1[12] = to_tf32(na1.w);
            }
            __syncthreads();
        }

        // ---- epilogue: 4 phases of 32 rows, stage C in smem, gate math ----
#pragma unroll
        for (int p = 0; p < 4; p++) {
            if (m0w == p) {
#pragma unroll
                for (int mi = 0; mi < 2; mi++)
#pragma unroll
                    for (int ni = 0; ni < 6; ni++) {
                        int col = n0 + 8 * ni + 2 * tq;
                        *(float2*)&Cs[(16 * mi + g) * 104 + col] =
                            make_float2(acc[mi][ni][0], acc[mi][ni][1]);
                        *(float2*)&Cs[(16 * mi + g + 8) * 104 + col] =
                            make_float2(acc[mi][ni][2], acc[mi][ni][3]);
                    }
            }
            __syncthreads();

#pragma unroll
            for (int i = tid; i < 32 * 32; i += 256) {
                int e = i & 31, r = i >> 5;
                int rg = rb + p * 32 + r;
                int eg = ecb + e;
                float hr = Cs[r * 104 + 3 * e]     + b_hh[eg];
                float hz = Cs[r * 104 + 3 * e + 1] + b_hh[NE + eg];
                float hn = Cs[r * 104 + 3 * e + 2] + b_hh[2 * NE + eg];
                int tok = tokens[rg * NT + t];
                const float* Gr = g_G + (size_t)tok * G3E;
                float ir = Gr[eg], iz = Gr[NE + eg], inn = Gr[2 * NE + eg];
                float rr = 1.f / (1.f + expf(-(ir + hr)));
                float zz = 1.f / (1.f + expf(-(iz + hz)));
                float nn = tanhf(inn + rr * hn);
                float hp = hin[(size_t)rg * NE + eg];
                hout[(size_t)rg * NE + eg] = (1.f - zz) * nn + zz * hp;
            }
            __syncthreads();
        }

        // all CTAs' hout writes must land before next step reads them
        grid_sync();
    }
}

// ---------------------------------------------------------------------------
// Generic tiled GEMM: C[Mr x Nc] = A[Mr x K] * Bm[Nc x K]^T + bias[Nc]
// ---------------------------------------------------------------------------
__global__ __launch_bounds__(256) void gemm64_abT(
    const float* __restrict__ A, const float* __restrict__ Bm,
    const float* __restrict__ bias, float* __restrict__ C, int Nc, int K)
{
    __shared__ float As[64][17];
    __shared__ float Bs[16][65];
    int tid = threadIdx.x;
    int r4 = tid >> 2, q = tid & 3;
    int ty = tid >> 4, tx = tid & 15;
    int rb = blockIdx.y * 64, cb = blockIdx.x * 64;

    float acc[4][4];
#pragma unroll
    for (int i = 0; i < 4; i++)
#pragma unroll
        for (int j = 0; j < 4; j++) acc[i][j] = 0.f;

    for (int k0 = 0; k0 < K; k0 += 16) {
        float4 av = *(const float4*)(A + (size_t)(rb + r4) * K + k0 + q * 4);
        As[r4][q * 4 + 0] = av.x; As[r4][q * 4 + 1] = av.y;
        As[r4][q * 4 + 2] = av.z; As[r4][q * 4 + 3] = av.w;
        float4 bv = *(const float4*)(Bm + (size_t)(cb + r4) * K + k0 + q * 4);
        Bs[q * 4 + 0][r4] = bv.x; Bs[q * 4 + 1][r4] = bv.y;
        Bs[q * 4 + 2][r4] = bv.z; Bs[q * 4 + 3][r4] = bv.w;
        __syncthreads();
#pragma unroll
        for (int kk = 0; kk < 16; kk++) {
            float a[4], b[4];
#pragma unroll
            for (int i = 0; i < 4; i++) a[i] = As[ty * 4 + i][kk];
#pragma unroll
            for (int j = 0; j < 4; j++) b[j] = Bs[kk][tx * 4 + j];
#pragma unroll
            for (int i = 0; i < 4; i++)
#pragma unroll
                for (int j = 0; j < 4; j++) acc[i][j] = fmaf(a[i], b[j], acc[i][j]);
        }
        __syncthreads();
    }
#pragma unroll
    for (int i = 0; i < 4; i++) {
        int row = rb + ty * 4 + i;
#pragma unroll
        for (int j = 0; j < 4; j++) {
            int col = cb + tx * 4 + j;
            C[(size_t)row * Nc + col] = acc[i][j] + bias[col];
        }
    }
}

__global__ void init_kernel(float* h0)
{
    int i = blockIdx.x * blockDim.x + threadIdx.x;
    if (i < NB * NE) h0[i] = 0.f;
    if (i == 0) { g_barCount = 0u; g_barGen = 0u; }
}

// ---------------------------------------------------------------------------
// psi init: split zc -> (re, im), complex_normalize per row.
// ---------------------------------------------------------------------------
__global__ __launch_bounds__(256) void psi_init_kernel()
{
    int b = blockIdx.x, tid = threadIdx.x;
    __shared__ float red[8];
    const float* zrow = g_zc + (size_t)b * 2 * NM;
    float ss = 0.f;
    for (int m = tid; m < NM; m += 256) {
        float re = zrow[m], im = zrow[NM + m];
        ss += re * re + im * im;
    }
    for (int o = 16; o; o >>= 1) ss += __shfl_xor_sync(0xffffffffu, ss, o);
    if ((tid & 31) == 0) red[tid >> 5] = ss;
    __syncthreads();
    if (tid < 8) {
        float v = red[tid];
        for (int o = 4; o; o >>= 1) v += __shfl_xor_sync(0xffu, v, o);
        if (tid == 0) red[0] = v;
    }
    __syncthreads();
    float inv = 1.f / sqrtf(red[0] + 1e-8f);
    for (int m = tid; m < NM; m += 256) {
        g_pr[(size_t)b * NM + m] = zrow[m] * inv;
        g_pi[(size_t)b * NM + m] = zrow[NM + m] * inv;
    }
}

// ---------------------------------------------------------------------------
// MZI layers: one block per batch row, psi row lives in SMEM for all 32 layers.
// ---------------------------------------------------------------------------
__device__ __forceinline__ void pair_apply(int a, int c, float tt, float pp, float rr,
                                           float* sre, float* sim)
{
    float st, ct; sincosf(tt, &st, &ct);
    float sp, cp; sincosf(pp, &sp, &cp);
    float sr, cr; sincosf(rr, &sr, &cr);
    float cpr = cp * cr - sp * sr;
    float spr = sp * cr + cp * sr;
    float u11r = ct * cpr, u11i = ct * spr;
    float u12r = -st * sp, u12i = st * cp;
    float u21r = -st * sr, u21i = st * cr;
    float u22  = ct;
    float v0r = sre[a], v0i = sim[a], v1r = sre[c], v1i = sim[c];
    float n0r = u11r * v0r - u11i * v0i + u12r * v1r - u12i * v1i;
    float n0i = u11r * v0i + u11i * v0r + u12r * v1i + u12i * v1r;
    float n1r = u21r * v0r - u21i * v0i + u22 * v1r;
    float n1i = u21r * v0i + u21i * v0r + u22 * v1i;
    sre[a] = n0r; sim[a] = n0i; sre[c] = n1r; sim[c] = n1i;
}

__global__ __launch_bounds__(512) void mzi_kernel(
    const float* __restrict__ phase, const float* __restrict__ te,
    const float* __restrict__ pe, const float* __restrict__ re_,
    const float* __restrict__ to, const float* __restrict__ po,
    const float* __restrict__ ro)
{
    __shared__ float sre[NM], sim[NM];
    __shared__ float red[16];
    int b = blockIdx.x, tid = threadIdx.x;
    sre[tid] = g_pr[(size_t)b * NM + tid];
    sre[tid + 512] = g_pr[(size_t)b * NM + tid + 512];
    sim[tid] = g_pi[(size_t)b * NM + tid];
    sim[tid + 512] = g_pi[(size_t)b * NM + tid + 512];
    __syncthreads();

    for (int l = 0; l < NL; l++) {
#pragma unroll
        for (int h = 0; h < 2; h++) {
            int mm = tid + h * 512;
            float s, c; sincosf(phase[l * NM + mm], &s, &c);
            float r0 = sre[mm], i0 = sim[mm];
            sre[mm] = r0 * c - i0 * s;
            sim[mm] = r0 * s + i0 * c;
        }
        __syncthreads();
        pair_apply(2 * tid, 2 * tid + 1,
                   te[l * NPE + tid], pe[l * NPE + tid], re_[l * NPE + tid], sre, sim);
        __syncthreads();
        if (tid < NPO)
            pair_apply(2 * tid + 1, 2 * tid + 2,
                       to[l * NPO + tid], po[l * NPO + tid], ro[l * NPO + tid], sre, sim);
        __syncthreads();
        float ss = sre[tid] * sre[tid] + sim[tid] * sim[tid]
                 + sre[tid + 512] * sre[tid + 512] + sim[tid + 512] * sim[tid + 512];
        for (int o = 16; o; o >>= 1) ss += __shfl_xor_sync(0xffffffffu, ss, o);
        if ((tid & 31) == 0) red[tid >> 5] = ss;
        __syncthreads();
        if (tid < 16) {
            float v = red[tid];
            for (int o = 8; o; o >>= 1) v += __shfl_xor_sync(0xffffu, v, o);
            if (tid == 0) red[0] = v;
        }
        __syncthreads();
        float inv = 1.f / sqrtf(red[0] + 1e-8f);
        sre[tid] *= inv; sim[tid] *= inv;
        sre[tid + 512] *= inv; sim[tid + 512] *= inv;
        __syncthreads();
    }

    g_pr[(size_t)b * NM + tid] = sre[tid];
    g_pr[(size_t)b * NM + tid + 512] = sre[tid + 512];
    g_pi[(size_t)b * NM + tid] = sim[tid];
    g_pi[(size_t)b * NM + tid + 512] = sim[tid + 512];
}

// ---------------------------------------------------------------------------
// Readout: amps = psi @ R^T (complex), out = log(|amps|^2 + 1e-12).
// ---------------------------------------------------------------------------
__global__ __launch_bounds__(256) void readout_kernel(
    const float* __restrict__ Rr, const float* __restrict__ Ri,
    float* __restrict__ out)
{
    __shared__ float Ar[64][17], Ai[64][17];
    __shared__ float Br[16][65], Bi[16][65];
    int tid = threadIdx.x;
    int r4 = tid >> 2, q = tid & 3;
    int ty = tid >> 4, tx = tid & 15;
    int rb = blockIdx.y * 64, cb = blockIdx.x * 64;

    float accr[4][4], acci[4][4];
#pragma unroll
    for (int i = 0; i < 4; i++)
#pragma unroll
        for (int j = 0; j < 4; j++) { accr[i][j] = 0.f; acci[i][j] = 0.f; }

    for (int k0 = 0; k0 < NM; k0 += 16) {
        float4 v;
        v = *(const float4*)(g_pr + (size_t)(rb + r4) * NM + k0 + q * 4);
        Ar[r4][q * 4 + 0] = v.x; Ar[r4][q * 4 + 1] = v.y;
        Ar[r4][q * 4 + 2] = v.z; Ar[r4][q * 4 + 3] = v.w;
        v = *(const float4*)(g_pi + (size_t)(rb + r4) * NM + k0 + q * 4);
        Ai[r4][q * 4 + 0] = v.x; Ai[r4][q * 4 + 1] = v.y;
        Ai[r4][q * 4 + 2] = v.z; Ai[r4][q * 4 + 3] = v.w;
        v = *(const float4*)(Rr + (size_t)(cb + r4) * NM + k0 + q * 4);
        Br[q * 4 + 0][r4] = v.x; Br[q * 4 + 1][r4] = v.y;
        Br[q * 4 + 2][r4] = v.z; Br[q * 4 + 3][r4] = v.w;
        v = *(const float4*)(Ri + (size_t)(cb + r4) * NM + k0 + q * 4);
        Bi[q * 4 + 0][r4] = v.x; Bi[q * 4 + 1][r4] = v.y;
        Bi[q * 4 + 2][r4] = v.z; Bi[q * 4 + 3][r4] = v.w;
        __syncthreads();
#pragma unroll
        for (int kk = 0; kk < 16; kk++) {
            float par[4], pai[4], wbr[4], wbi[4];
#pragma unroll
            for (int i = 0; i < 4; i++) { par[i] = Ar[ty * 4 + i][kk]; pai[i] = Ai[ty * 4 + i][kk]; }
#pragma unroll
            for (int j = 0; j < 4; j++) { wbr[j] = Br[kk][tx * 4 + j]; wbi[j] = Bi[kk][tx * 4 + j]; }
#pragma unroll
            for (int i = 0; i < 4; i++)
#pragma unroll
                for (int j = 0; j < 4; j++) {
                    accr[i][j] = fmaf(par[i], wbr[j], accr[i][j]);
                    accr[i][j] = fmaf(-pai[i], wbi[j], accr[i][j]);
                    acci[i][j] = fmaf(par[i], wbi[j], acci[i][j]);
                    acci[i][j] = fmaf(pai[i], wbr[j], acci[i][j]);
                }
        }
        __syncthreads();
    }
#pragma unroll
    for (int i = 0; i < 4; i++) {
        int row = rb + ty * 4 + i;
#pragma unroll
        for (int j = 0; j < 4; j++) {
            int col = cb + tx * 4 + j;
            float ar = accr[i][j], ai = acci[i][j];
            out[(size_t)row * NV + col] = logf(ar * ar + ai * ai + 1e-12f);
        }
    }
}

// ---------------------------------------------------------------------------
// Row-wise logsumexp, subtract in place.
// ---------------------------------------------------------------------------
__global__ __launch_bounds__(256) void lse_kernel(float* __restrict__ out)
{
    int b = blockIdx.x, tid = threadIdx.x;
    __shared__ float red[8];
    float* row = out + (size_t)b * NV;

    float mx = -INFINITY;
    for (int v = tid; v < NV; v += 256) mx = fmaxf(mx, row[v]);
    for (int o = 16; o; o >>= 1) mx = fmaxf(mx, __shfl_xor_sync(0xffffffffu, mx, o));
    if ((tid & 31) == 0) red[tid >> 5] = mx;
    __syncthreads();
    if (tid < 8) {
        float v = red[tid];
        for (int o = 4; o; o >>= 1) v = fmaxf(v, __shfl_xor_sync(0xffu, v, o));
        if (tid == 0) red[0] = v;
    }
    __syncthreads();
    mx = red[0];
    __syncthreads();

    float se = 0.f;
    for (int v = tid; v < NV; v += 256) se += expf(row[v] - mx);
    for (int o = 16; o; o >>= 1) se += __shfl_xor_sync(0xffffffffu, se, o);
    if ((tid & 31) == 0) red[tid >> 5] = se;
    __syncthreads();
    if (tid < 8) {
        float v = red[tid];
        for (int o = 4; o; o >>= 1) v += __shfl_xor_sync(0xffu, v, o);
        if (tid == 0) red[0] = v;
    }
    __syncthreads();
    float lse = mx + logf(red[0]);
    for (int v = tid; v < NV; v += 256) row[v] -= lse;
}

// ---------------------------------------------------------------------------
extern "C" void kernel_launch(void* const* d_in, const int* in_sizes, int n_in,
                              void* d_out, int out_size)
{
    const int*   tokens = (const int*)d_in[0];
    const float* embed  = (const float*)d_in[1];
    const float* W_ih   = (const float*)d_in[2];
    const float* W_hh   = (const float*)d_in[3];
    const float* b_ih   = (const float*)d_in[4];
    const float* b_hh   = (const float*)d_in[5];
    const float* Wc     = (const float*)d_in[6];
    const float* bc     = (const float*)d_in[7];
    const float* phase  = (const float*)d_in[8];
    const float* te     = (const float*)d_in[9];
    const float* pe     = (const float*)d_in[10];
    const float* re_    = (const float*)d_in[11];
    const float* to     = (const float*)d_in[12];
    const float* po     = (const float*)d_in[13];
    const float* ro     = (const float*)d_in[14];
    const float* Rr     = (const float*)d_in[15];
    const float* Ri     = (const float*)d_in[16];
    float* out = (float*)d_out;

    static float* pG = nullptr;
    static float* pH = nullptr;
    static float* pZC = nullptr;
    if (!pG) {
        cudaGetSymbolAddress((void**)&pG, g_G);
        cudaGetSymbolAddress((void**)&pH, g_h);
        cudaGetSymbolAddress((void**)&pZC, g_zc);
        cudaFuncSetAttribute(gru_persist,
                             cudaFuncAttributeMaxDynamicSharedMemorySize, SMEM_BYTES);
    }
    float* pH0 = pH;
    float* pH1 = pH + NB * NE;

    // 1. Token gate table: G = embed @ W_ih^T + b_ih  (V x 3E)
    gemm64_abT<<<dim3(G3E / 64, NV / 64), 256>>>(embed, W_ih, b_ih, pG, G3E, NE);

    // 2. h0 = 0 + barrier state reset
    init_kernel<<<(NB * NE + 255) / 256, 256>>>(pH0);

    // 3. Whole GRU recurrence in ONE persistent kernel (frag-permuted smem)
    gru_persist<<<dim3(16, 8), 256, SMEM_BYTES>>>(pH0, pH1, W_hh, b_hh, tokens);

    // 4. zc = h @ Wc^T + bc, then normalized complex psi (NT even -> h in pH0)
    gemm64_abT<<<dim3(2 * NM / 64, NB / 64), 256>>>(pH0, Wc, bc, pZC, 2 * NM, NE);
    psi_init_kernel<<<NB, 256>>>();

    // 5. 32 MZI layers, persistent row in SMEM
    mzi_kernel<<<NB, 512>>>(phase, te, pe, re_, to, po, ro);

    // 6. Readout complex GEMM + log|.|^2, then row logsumexp
    readout_kernel<<<dim3(NV / 64, NB / 64), 256>>>(Rr, Ri, out);
    lse_kernel<<<NB, 256>>>(out);
}

// round 10
// speedup vs baseline: 1.4066x; 1.4066x over previous
#include <cuda_runtime.h>
#include <math.h>

// Problem dims
#define NB 1024   // batch
#define NT 64     // time steps
#define NV 1024   // vocab
#define NE 512    // embed dim
#define NM 1024   // modes
#define NL 32     // MZI layers
#define NPE 512   // even pairs
#define NPO 511   // odd pairs
#define G3E 1536  // 3*NE

// Scratch (no allocations allowed -> __device__ globals)
__device__ float g_G[NV * G3E];       // token gate table: embed@W_ih^T + b_ih
__device__ float g_h[2][NB * NE];     // GRU hidden double buffer
__device__ float g_zc[NB * 2 * NM];   // h@Wc^T + bc
__device__ float g_pr[NB * NM];       // psi real
__device__ float g_pi[NB * NM];       // psi imag
__device__ unsigned g_barCount;       // grid barrier state
__device__ unsigned g_barGen;

// ---------------------------------------------------------------------------
// tf32 helpers
// ---------------------------------------------------------------------------
__device__ __forceinline__ float to_tf32(float x) {
    unsigned u;
    asm("cvt.rna.tf32.f32 %0, %1;" : "=r"(u) : "f"(x));
    return __uint_as_float(u);
}

__device__ __forceinline__ void mma_tf32(float* c, const unsigned* a, const unsigned* b) {
    asm("mma.sync.aligned.m16n8k8.row.col.f32.tf32.tf32.f32 "
        "{%0,%1,%2,%3}, {%4,%5,%6,%7}, {%8,%9}, {%0,%1,%2,%3};"
        : "+f"(c[0]), "+f"(c[1]), "+f"(c[2]), "+f"(c[3])
        : "r"(a[0]), "r"(a[1]), "r"(a[2]), "r"(a[3]), "r"(b[0]), "r"(b[1]));
}

// ---------------------------------------------------------------------------
// Grid-wide spin barrier (all 128 CTAs wave-1 resident: 1 CTA/SM via smem).
// ---------------------------------------------------------------------------
#define NCTA 128
__device__ __forceinline__ void grid_sync()
{
    __threadfence();
    __syncthreads();
    if (threadIdx.x == 0) {
        unsigned gen = *(volatile unsigned*)&g_barGen;
        if (atomicAdd(&g_barCount, 1u) == NCTA - 1) {
            g_barCount = 0;
            __threadfence();
            atomicExch(&g_barGen, gen + 1u);
        } else {
            while (*(volatile unsigned*)&g_barGen == gen) { __nanosleep(64); }
            __threadfence();
        }
    }
    __syncthreads();
}

// ---------------------------------------------------------------------------
// Persistent GRU, 512 threads (16 warps = 4/SMSP), K-split warp spec.
//
// CTA tile: 128 batch rows x 96 gate cols (32 hidden units, gates interleaved
// e*3+g). Warp (kg, m, n): kg = w>>3 handles k8-substep ks==kg of each 16-wide
// k-tile; m = (w>>1)&3 -> 32-row band; n = w&1 -> 48-col band. Partial sums
// over the two kg groups are reduced in the phased epilogue.
//
// A (h): row-major smem, stride 20 (R4-proven conflict-free for both the
//   float4 stores and the 4xLDS.32 fragment loads). Double-buffered.
// W: resident all 64 steps, frag-ordered (R8-proven consumer path):
//   Ws[((n8*64 + k8)*32 + 4*g + tq)*2 + br] = W[n=8*n8+g][k=8*k8+tq+4*br]
//   -> one LDS.64 per lane per B-frag, conflict-free; built once.
// ---------------------------------------------------------------------------
#define WS_FLOATS (96 * 512)            // 49152 floats
#define AS_STAGE  (128 * 20)            // 2560 floats per stage
#define SMEM_FLOATS (WS_FLOATS + 2 * AS_STAGE)
#define SMEM_BYTES (SMEM_FLOATS * 4)    // 217,088 B

__global__ __launch_bounds__(512, 1) void gru_persist(
    float* __restrict__ h0, float* __restrict__ h1,
    const float* __restrict__ W_hh, const float* __restrict__ b_hh,
    const int* __restrict__ tokens)
{
    extern __shared__ float smem[];
    float* Ws = smem;                    // frag-ordered W slice
    float* As = smem + WS_FLOATS;        // [2][128*20]
    float* Cs = As;                      // epilogue staging reuses A space

    int tid = threadIdx.x;
    int lane = tid & 31, w = tid >> 5;   // 16 warps
    int g = lane >> 2, tq = lane & 3;
    int kg = w >> 3;                     // k-substep group (ks == kg)
    int wl = w & 7;
    int m0w = wl >> 1;                   // warp m-band (0..3)
    int m0 = m0w * 32;
    int n0 = (wl & 1) * 48;              // warp col base (0 or 48)
    int n8base = (wl & 1) * 6;
    int rb = blockIdx.y * 128;           // global row base
    int ecb = blockIdx.x * 32;           // global e base
    int cb = ecb * 3;                    // global gate-col base

    // ---- one-time: build frag-ordered, gate-interleaved, tf32 W slice ----
    for (int idx = tid; idx < 96 * 512; idx += 512) {
        int nl = idx >> 9;               // 0..95
        int k = idx & 511;
        int col = cb + nl;               // interleaved gate col
        int e = col / 3, gg = col - 3 * e;
        float v = to_tf32(W_hh[(size_t)(gg * NE + e) * NE + k]);
        int n8 = nl >> 3, bg = nl & 7;
        int k8 = k >> 3, btq = k & 3, br = (k >> 2) & 1;
        Ws[((n8 * 64 + k8) * 32 + 4 * bg + btq) * 2 + br] = v;
    }
    __syncthreads();

    // A loader: 512 threads, one float4 each per 128x16 tile
    int aRow = tid >> 2, aQ = tid & 3;

    for (int t = 0; t < NT; t++) {
        const float* hin = (t & 1) ? h1 : h0;
        float* hout      = (t & 1) ? h0 : h1;
        const float* Ag = hin + (size_t)rb * NE;

        // preload k-tile 0 into stage 0
        {
            float4 a0 = *(const float4*)(Ag + (size_t)aRow * NE + aQ * 4);
            float* d = As + aRow * 20 + aQ * 4;
            d[0] = to_tf32(a0.x); d[1] = to_tf32(a0.y);
            d[2] = to_tf32(a0.z); d[3] = to_tf32(a0.w);
        }
        __syncthreads();

        float acc[2][6][4];
#pragma unroll
        for (int mi = 0; mi < 2; mi++)
#pragma unroll
            for (int ni = 0; ni < 6; ni++)
#pragma unroll
                for (int j = 0; j < 4; j++) acc[mi][ni][j] = 0.f;

        for (int kt = 0; kt < 32; kt++) {
            const float* Acur = As + (kt & 1) * AS_STAGE;
            float4 na;
            if (kt < 31) {
                int k0 = (kt + 1) * 16;
                na = *(const float4*)(Ag + (size_t)aRow * NE + k0 + aQ * 4);
            }
            // this warp's k8 substep: ks == kg
            {
                int k8 = kt * 2 + kg;
                unsigned af[2][4];
#pragma unroll
                for (int mi = 0; mi < 2; mi++) {
                    const float* ap = Acur + (m0 + 16 * mi) * 20 + kg * 8;
                    af[mi][0] = __float_as_uint(ap[g * 20 + tq]);
                    af[mi][1] = __float_as_uint(ap[(g + 8) * 20 + tq]);
                    af[mi][2] = __float_as_uint(ap[g * 20 + tq + 4]);
                    af[mi][3] = __float_as_uint(ap[(g + 8) * 20 + tq + 4]);
                }
#pragma unroll
                for (int ni = 0; ni < 6; ni++) {
                    float2 bv = *(const float2*)(Ws + (((n8base + ni) * 64 + k8) * 32 + lane) * 2);
                    unsigned bf[2] = { __float_as_uint(bv.x), __float_as_uint(bv.y) };
                    mma_tf32(acc[0][ni], af[0], bf);
                    mma_tf32(acc[1][ni], af[1], bf);
                }
            }
            if (kt < 31) {
                float* d = As + ((kt + 1) & 1) * AS_STAGE + aRow * 20 + aQ * 4;
                d[0] = to_tf32(na.x); d[1] = to_tf32(na.y);
                d[2] = to_tf32(na.z); d[3] = to_tf32(na.w);
            }
            __syncthreads();
        }

        // ---- epilogue: 4 phases of 32 rows; kg0 stores, kg1 adds, gates ----
#pragma unroll
        for (int p = 0; p < 4; p++) {
            if (m0w == p && kg == 0) {
#pragma unroll
                for (int mi = 0; mi < 2; mi++)
#pragma unroll
                    for (int ni = 0; ni < 6; ni++) {
                        int col = n0 + 8 * ni + 2 * tq;
                        *(float2*)&Cs[(16 * mi + g) * 104 + col] =
                            make_float2(acc[mi][ni][0], acc[mi][ni][1]);
                        *(float2*)&Cs[(16 * mi + g + 8) * 104 + col] =
                            make_float2(acc[mi][ni][2], acc[mi][ni][3]);
                    }
            }
            __syncthreads();
            if (m0w == p && kg == 1) {
#pragma unroll
                for (int mi = 0; mi < 2; mi++)
#pragma unroll
                    for (int ni = 0; ni < 6; ni++) {
                        int col = n0 + 8 * ni + 2 * tq;
                        float2* c0 = (float2*)&Cs[(16 * mi + g) * 104 + col];
                        float2 v0 = *c0;
                        v0.x += acc[mi][ni][0]; v0.y += acc[mi][ni][1];
                        *c0 = v0;
                        float2* c1 = (float2*)&Cs[(16 * mi + g + 8) * 104 + col];
                        float2 v1 = *c1;
                        v1.x += acc[mi][ni][2]; v1.y += acc[mi][ni][3];
                        *c1 = v1;
                    }
            }
            __syncthreads();

            for (int i = tid; i < 32 * 32; i += 512) {
                int e = i & 31, r = i >> 5;
                int rg = rb + p * 32 + r;
                int eg = ecb + e;
                float hr = Cs[r * 104 + 3 * e]     + b_hh[eg];
                float hz = Cs[r * 104 + 3 * e + 1] + b_hh[NE + eg];
                float hn = Cs[r * 104 + 3 * e + 2] + b_hh[2 * NE + eg];
                int tok = tokens[rg * NT + t];
                const float* Gr = g_G + (size_t)tok * G3E;
                float ir = Gr[eg], iz = Gr[NE + eg], inn = Gr[2 * NE + eg];
                float rr = 1.f / (1.f + expf(-(ir + hr)));
                float zz = 1.f / (1.f + expf(-(iz + hz)));
                float nn = tanhf(inn + rr * hn);
                float hp = hin[(size_t)rg * NE + eg];
                hout[(size_t)rg * NE + eg] = (1.f - zz) * nn + zz * hp;
            }
            __syncthreads();
        }

        // all CTAs' hout writes must land before next step reads them
        grid_sync();
    }
}

// ---------------------------------------------------------------------------
// Generic tiled GEMM: C[Mr x Nc] = A[Mr x K] * Bm[Nc x K]^T + bias[Nc]
// ---------------------------------------------------------------------------
__global__ __launch_bounds__(256) void gemm64_abT(
    const float* __restrict__ A, const float* __restrict__ Bm,
    const float* __restrict__ bias, float* __restrict__ C, int Nc, int K)
{
    __shared__ float As[64][17];
    __shared__ float Bs[16][65];
    int tid = threadIdx.x;
    int r4 = tid >> 2, q = tid & 3;
    int ty = tid >> 4, tx = tid & 15;
    int rb = blockIdx.y * 64, cb = blockIdx.x * 64;

    float acc[4][4];
#pragma unroll
    for (int i = 0; i < 4; i++)
#pragma unroll
        for (int j = 0; j < 4; j++) acc[i][j] = 0.f;

    for (int k0 = 0; k0 < K; k0 += 16) {
        float4 av = *(const float4*)(A + (size_t)(rb + r4) * K + k0 + q * 4);
        As[r4][q * 4 + 0] = av.x; As[r4][q * 4 + 1] = av.y;
        As[r4][q * 4 + 2] = av.z; As[r4][q * 4 + 3] = av.w;
        float4 bv = *(const float4*)(Bm + (size_t)(cb + r4) * K + k0 + q * 4);
        Bs[q * 4 + 0][r4] = bv.x; Bs[q * 4 + 1][r4] = bv.y;
        Bs[q * 4 + 2][r4] = bv.z; Bs[q * 4 + 3][r4] = bv.w;
        __syncthreads();
#pragma unroll
        for (int kk = 0; kk < 16; kk++) {
            float a[4], b[4];
#pragma unroll
            for (int i = 0; i < 4; i++) a[i] = As[ty * 4 + i][kk];
#pragma unroll
            for (int j = 0; j < 4; j++) b[j] = Bs[kk][tx * 4 + j];
#pragma unroll
            for (int i = 0; i < 4; i++)
#pragma unroll
                for (int j = 0; j < 4; j++) acc[i][j] = fmaf(a[i], b[j], acc[i][j]);
        }
        __syncthreads();
    }
#pragma unroll
    for (int i = 0; i < 4; i++) {
        int row = rb + ty * 4 + i;
#pragma unroll
        for (int j = 0; j < 4; j++) {
            int col = cb + tx * 4 + j;
            C[(size_t)row * Nc + col] = acc[i][j] + bias[col];
        }
    }
}

__global__ void init_kernel(float* h0)
{
    int i = blockIdx.x * blockDim.x + threadIdx.x;
    if (i < NB * NE) h0[i] = 0.f;
    if (i == 0) { g_barCount = 0u; g_barGen = 0u; }
}

// ---------------------------------------------------------------------------
// psi init: split zc -> (re, im), complex_normalize per row.
// ---------------------------------------------------------------------------
__global__ __launch_bounds__(256) void psi_init_kernel()
{
    int b = blockIdx.x, tid = threadIdx.x;
    __shared__ float red[8];
    const float* zrow = g_zc + (size_t)b * 2 * NM;
    float ss = 0.f;
    for (int m = tid; m < NM; m += 256) {
        float re = zrow[m], im = zrow[NM + m];
        ss += re * re + im * im;
    }
    for (int o = 16; o; o >>= 1) ss += __shfl_xor_sync(0xffffffffu, ss, o);
    if ((tid & 31) == 0) red[tid >> 5] = ss;
    __syncthreads();
    if (tid < 8) {
        float v = red[tid];
        for (int o = 4; o; o >>= 1) v += __shfl_xor_sync(0xffu, v, o);
        if (tid == 0) red[0] = v;
    }
    __syncthreads();
    float inv = 1.f / sqrtf(red[0] + 1e-8f);
    for (int m = tid; m < NM; m += 256) {
        g_pr[(size_t)b * NM + m] = zrow[m] * inv;
        g_pi[(size_t)b * NM + m] = zrow[NM + m] * inv;
    }
}

// ---------------------------------------------------------------------------
// MZI layers: one block per batch row, psi row lives in SMEM for all 32 layers.
// ---------------------------------------------------------------------------
__device__ __forceinline__ void pair_apply(int a, int c, float tt, float pp, float rr,
                                           float* sre, float* sim)
{
    float st, ct; sincosf(tt, &st, &ct);
    float sp, cp; sincosf(pp, &sp, &cp);
    float sr, cr; sincosf(rr, &sr, &cr);
    float cpr = cp * cr - sp * sr;
    float spr = sp * cr + cp * sr;
    float u11r = ct * cpr, u11i = ct * spr;
    float u12r = -st * sp, u12i = st * cp;
    float u21r = -st * sr, u21i = st * cr;
    float u22  = ct;
    float v0r = sre[a], v0i = sim[a], v1r = sre[c], v1i = sim[c];
    float n0r = u11r * v0r - u11i * v0i + u12r * v1r - u12i * v1i;
    float n0i = u11r * v0i + u11i * v0r + u12r * v1i + u12i * v1r;
    float n1r = u21r * v0r - u21i * v0i + u22 * v1r;
    float n1i = u21r * v0i + u21i * v0r + u22 * v1i;
    sre[a] = n0r; sim[a] = n0i; sre[c] = n1r; sim[c] = n1i;
}

__global__ __launch_bounds__(512) void mzi_kernel(
    const float* __restrict__ phase, const float* __restrict__ te,
    const float* __restrict__ pe, const float* __restrict__ re_,
    const float* __restrict__ to, const float* __restrict__ po,
    const float* __restrict__ ro)
{
    __shared__ float sre[NM], sim[NM];
    __shared__ float red[16];
    int b = blockIdx.x, tid = threadIdx.x;
    sre[tid] = g_pr[(size_t)b * NM + tid];
    sre[tid + 512] = g_pr[(size_t)b * NM + tid + 512];
    sim[tid] = g_pi[(size_t)b * NM + tid];
    sim[tid + 512] = g_pi[(size_t)b * NM + tid + 512];
    __syncthreads();

    for (int l = 0; l < NL; l++) {
#pragma unroll
        for (int h = 0; h < 2; h++) {
            int mm = tid + h * 512;
            float s, c; sincosf(phase[l * NM + mm], &s, &c);
            float r0 = sre[mm], i0 = sim[mm];
            sre[mm] = r0 * c - i0 * s;
            sim[mm] = r0 * s + i0 * c;
        }
        __syncthreads();
        pair_apply(2 * tid, 2 * tid + 1,
                   te[l * NPE + tid], pe[l * NPE + tid], re_[l * NPE + tid], sre, sim);
        __syncthreads();
        if (tid < NPO)
            pair_apply(2 * tid + 1, 2 * tid + 2,
                       to[l * NPO + tid], po[l * NPO + tid], ro[l * NPO + tid], sre, sim);
        __syncthreads();
        float ss = sre[tid] * sre[tid] + sim[tid] * sim[tid]
                 + sre[tid + 512] * sre[tid + 512] + sim[tid + 512] * sim[tid + 512];
        for (int o = 16; o; o >>= 1) ss += __shfl_xor_sync(0xffffffffu, ss, o);
        if ((tid & 31) == 0) red[tid >> 5] = ss;
        __syncthreads();
        if (tid < 16) {
            float v = red[tid];
            for (int o = 8; o; o >>= 1) v += __shfl_xor_sync(0xffffu, v, o);
            if (tid == 0) red[0] = v;
        }
        __syncthreads();
        float inv = 1.f / sqrtf(red[0] + 1e-8f);
        sre[tid] *= inv; sim[tid] *= inv;
        sre[tid + 512] *= inv; sim[tid + 512] *= inv;
        __syncthreads();
    }

    g_pr[(size_t)b * NM + tid] = sre[tid];
    g_pr[(size_t)b * NM + tid + 512] = sre[tid + 512];
    g_pi[(size_t)b * NM + tid] = sim[tid];
    g_pi[(size_t)b * NM + tid + 512] = sim[tid + 512];
}

// ---------------------------------------------------------------------------
// Readout: amps = psi @ R^T (complex), out = log(|amps|^2 + 1e-12).
// ---------------------------------------------------------------------------
__global__ __launch_bounds__(256) void readout_kernel(
    const float* __restrict__ Rr, const float* __restrict__ Ri,
    float* __restrict__ out)
{
    __shared__ float Ar[64][17], Ai[64][17];
    __shared__ float Br[16][65], Bi[16][65];
    int tid = threadIdx.x;
    int r4 = tid >> 2, q = tid & 3;
    int ty = tid >> 4, tx = tid & 15;
    int rb = blockIdx.y * 64, cb = blockIdx.x * 64;

    float accr[4][4], acci[4][4];
#pragma unroll
    for (int i = 0; i < 4; i++)
#pragma unroll
        for (int j = 0; j < 4; j++) { accr[i][j] = 0.f; acci[i][j] = 0.f; }

    for (int k0 = 0; k0 < NM; k0 += 16) {
        float4 v;
        v = *(const float4*)(g_pr + (size_t)(rb + r4) * NM + k0 + q * 4);
        Ar[r4][q * 4 + 0] = v.x; Ar[r4][q * 4 + 1] = v.y;
        Ar[r4][q * 4 + 2] = v.z; Ar[r4][q * 4 + 3] = v.w;
        v = *(const float4*)(g_pi + (size_t)(rb + r4) * NM + k0 + q * 4);
        Ai[r4][q * 4 + 0] = v.x; Ai[r4][q * 4 + 1] = v.y;
        Ai[r4][q * 4 + 2] = v.z; Ai[r4][q * 4 + 3] = v.w;
        v = *(const float4*)(Rr + (size_t)(cb + r4) * NM + k0 + q * 4);
        Br[q * 4 + 0][r4] = v.x; Br[q * 4 + 1][r4] = v.y;
        Br[q * 4 + 2][r4] = v.z; Br[q * 4 + 3][r4] = v.w;
        v = *(const float4*)(Ri + (size_t)(cb + r4) * NM + k0 + q * 4);
        Bi[q * 4 + 0][r4] = v.x; Bi[q * 4 + 1][r4] = v.y;
        Bi[q * 4 + 2][r4] = v.z; Bi[q * 4 + 3][r4] = v.w;
        __syncthreads();
#pragma unroll
        for (int kk = 0; kk < 16; kk++) {
            float par[4], pai[4], wbr[4], wbi[4];
#pragma unroll
            for (int i = 0; i < 4; i++) { par[i] = Ar[ty * 4 + i][kk]; pai[i] = Ai[ty * 4 + i][kk]; }
#pragma unroll
            for (int j = 0; j < 4; j++) { wbr[j] = Br[kk][tx * 4 + j]; wbi[j] = Bi[kk][tx * 4 + j]; }
#pragma unroll
            for (int i = 0; i < 4; i++)
#pragma unroll
                for (int j = 0; j < 4; j++) {
                    accr[i][j] = fmaf(par[i], wbr[j], accr[i][j]);
                    accr[i][j] = fmaf(-pai[i], wbi[j], accr[i][j]);
                    acci[i][j] = fmaf(par[i], wbi[j], acci[i][j]);
                    acci[i][j] = fmaf(pai[i], wbr[j], acci[i][j]);
                }
        }
        __syncthreads();
    }
#pragma unroll
    for (int i = 0; i < 4; i++) {
        int row = rb + ty * 4 + i;
#pragma unroll
        for (int j = 0; j < 4; j++) {
            int col = cb + tx * 4 + j;
            float ar = accr[i][j], ai = acci[i][j];
            out[(size_t)row * NV + col] = logf(ar * ar + ai * ai + 1e-12f);
        }
    }
}

// ---------------------------------------------------------------------------
// Row-wise logsumexp, subtract in place.
// ---------------------------------------------------------------------------
__global__ __launch_bounds__(256) void lse_kernel(float* __restrict__ out)
{
    int b = blockIdx.x, tid = threadIdx.x;
    __shared__ float red[8];
    float* row = out + (size_t)b * NV;

    float mx = -INFINITY;
    for (int v = tid; v < NV; v += 256) mx = fmaxf(mx, row[v]);
    for (int o = 16; o; o >>= 1) mx = fmaxf(mx, __shfl_xor_sync(0xffffffffu, mx, o));
    if ((tid & 31) == 0) red[tid >> 5] = mx;
    __syncthreads();
    if (tid < 8) {
        float v = red[tid];
        for (int o = 4; o; o >>= 1) v = fmaxf(v, __shfl_xor_sync(0xffu, v, o));
        if (tid == 0) red[0] = v;
    }
    __syncthreads();
    mx = red[0];
    __syncthreads();

    float se = 0.f;
    for (int v = tid; v < NV; v += 256) se += expf(row[v] - mx);
    for (int o = 16; o; o >>= 1) se += __shfl_xor_sync(0xffffffffu, se, o);
    if ((tid & 31) == 0) red[tid >> 5] = se;
    __syncthreads();
    if (tid < 8) {
        float v = red[tid];
        for (int o = 4; o; o >>= 1) v += __shfl_xor_sync(0xffu, v, o);
        if (tid == 0) red[0] = v;
    }
    __syncthreads();
    float lse = mx + logf(red[0]);
    for (int v = tid; v < NV; v += 256) row[v] -= lse;
}

// ---------------------------------------------------------------------------
extern "C" void kernel_launch(void* const* d_in, const int* in_sizes, int n_in,
                              void* d_out, int out_size)
{
    const int*   tokens = (const int*)d_in[0];
    const float* embed  = (const float*)d_in[1];
    const float* W_ih   = (const float*)d_in[2];
    const float* W_hh   = (const float*)d_in[3];
    const float* b_ih   = (const float*)d_in[4];
    const float* b_hh   = (const float*)d_in[5];
    const float* Wc     = (const float*)d_in[6];
    const float* bc     = (const float*)d_in[7];
    const float* phase  = (const float*)d_in[8];
    const float* te     = (const float*)d_in[9];
    const float* pe     = (const float*)d_in[10];
    const float* re_    = (const float*)d_in[11];
    const float* to     = (const float*)d_in[12];
    const float* po     = (const float*)d_in[13];
    const float* ro     = (const float*)d_in[14];
    const float* Rr     = (const float*)d_in[15];
    const float* Ri     = (const float*)d_in[16];
    float* out = (float*)d_out;

    static float* pG = nullptr;
    static float* pH = nullptr;
    static float* pZC = nullptr;
    if (!pG) {
        cudaGetSymbolAddress((void**)&pG, g_G);
        cudaGetSymbolAddress((void**)&pH, g_h);
        cudaGetSymbolAddress((void**)&pZC, g_zc);
        cudaFuncSetAttribute(gru_persist,
                             cudaFuncAttributeMaxDynamicSharedMemorySize, SMEM_BYTES);
    }
    float* pH0 = pH;
    float* pH1 = pH + NB * NE;

    // 1. Token gate table: G = embed @ W_ih^T + b_ih  (V x 3E)
    gemm64_abT<<<dim3(G3E / 64, NV / 64), 256>>>(embed, W_ih, b_ih, pG, G3E, NE);

    // 2. h0 = 0 + barrier state reset
    init_kernel<<<(NB * NE + 255) / 256, 256>>>(pH0);

    // 3. Whole GRU recurrence in ONE persistent kernel (16 warps, K-split)
    gru_persist<<<dim3(16, 8), 512, SMEM_BYTES>>>(pH0, pH1, W_hh, b_hh, tokens);

    // 4. zc = h @ Wc^T + bc, then normalized complex psi (NT even -> h in pH0)
    gemm64_abT<<<dim3(2 * NM / 64, NB / 64), 256>>>(pH0, Wc, bc, pZC, 2 * NM, NE);
    psi_init_kernel<<<NB, 256>>>();

    // 5. 32 MZI layers, persistent row in SMEM
    mzi_kernel<<<NB, 512>>>(phase, te, pe, re_, to, po, ro);

    // 6. Readout complex GEMM + log|.|^2, then row logsumexp
    readout_kernel<<<dim3(NV / 64, NB / 64), 256>>>(Rr, Ri, out);
    lse_kernel<<<NB, 256>>>(out);
}

// round 12
// speedup vs baseline: 1.7189x; 1.2220x over previous
#include <cuda_runtime.h>
#include <cuda_fp16.h>
#include <math.h>
#include <string.h>

// Problem dims
#define NB 1024   // batch
#define NT 64     // time steps
#define NV 1024   // vocab
#define NE 512    // embed dim
#define NM 1024   // modes
#define NL 32     // MZI layers
#define NPE 512   // even pairs
#define NPO 511   // odd pairs
#define G3E 1536  // 3*NE

// Scratch (no allocations allowed -> __device__ globals)
__device__ float g_G[NV * G3E];       // token gate table: embed@W_ih^T + b_ih
__device__ float g_h[2][NB * NE];     // GRU hidden double buffer
__device__ float g_zc[NB * 2 * NM];   // h@Wc^T + bc
__device__ float g_pr[NB * NM];       // psi real
__device__ float g_pi[NB * NM];       // psi imag
__device__ unsigned g_barCount[8];    // per-band barrier state
__device__ unsigned g_barGen[8];

// ---------------------------------------------------------------------------
// fp16 helpers
// ---------------------------------------------------------------------------
__device__ __forceinline__ unsigned h2u(__half2 h) {
    unsigned u;
    memcpy(&u, &h, 4);
    return u;
}

__device__ __forceinline__ void mma_f16(float* c, const unsigned* a, const unsigned* b) {
    asm("mma.sync.aligned.m16n8k16.row.col.f32.f16.f16.f32 "
        "{%0,%1,%2,%3}, {%4,%5,%6,%7}, {%8,%9}, {%0,%1,%2,%3};"
        : "+f"(c[0]), "+f"(c[1]), "+f"(c[2]), "+f"(c[3])
        : "r"(a[0]), "r"(a[1]), "r"(a[2]), "r"(a[3]), "r"(b[0]), "r"(b[1]));
}

__device__ __forceinline__ float fast_sigmoid(float x) {
    return 1.f / (1.f + __expf(-x));
}
__device__ __forceinline__ float fast_tanh(float x) {
    x = fminf(15.f, fmaxf(-15.f, x));
    float e2 = __expf(2.f * x);
    return (e2 - 1.f) / (e2 + 1.f);
}

// ---------------------------------------------------------------------------
// Per-band grid barrier: the GRU recurrence only couples the 16 CTAs that
// share blockIdx.y (they produce/consume the same 128 h rows). All 128 CTAs
// are wave-1 resident (1 CTA/SM) so spinning is safe.
// ---------------------------------------------------------------------------
#define NCTA_BAND 16
__device__ __forceinline__ void band_sync(int band)
{
    __threadfence();
    __syncthreads();
    if (threadIdx.x == 0) {
        unsigned gen = *(volatile unsigned*)&g_barGen[band];
        if (atomicAdd(&g_barCount[band], 1u) == NCTA_BAND - 1) {
            g_barCount[band] = 0;
            __threadfence();
            atomicExch(&g_barGen[band], gen + 1u);
        } else {
            while (*(volatile unsigned*)&g_barGen[band] == gen) { __nanosleep(32); }
            __threadfence();
        }
    }
    __syncthreads();
}

// ---------------------------------------------------------------------------
// Persistent GRU, fp16 m16n8k16, 512 threads (16 warps), K-split by k16-half.
//
// CTA tile: 128 batch rows x 96 gate cols (32 hidden units, gates interleaved
// e*3+g). Warp (kg, m, n): kg = w>>3 handles k16-tile kt = 2*kt2 + kg of each
// 32-wide staged pair; m=(w>>1)&3 -> 32-row band; n=w&1 -> 48-col band.
//
// W resident in SMEM all 64 steps as fp16 in B-fragment order:
//   [n8:12][kt:32][lane:32][4 halves]   (reg = kk>>3, tq = (kk>>1)&3, h = kk&1,
//    lane = 4*(n&7) + tq)  -> one LDS.64 per (n8,kt) frag, conflict-free.
// A staged as fp16 row-major, 32 cols/stage, stride 40 halves (80B):
//   frag loads 4x LDS.32, banks (20g + 8kg + tq) % 32 all-distinct.
// ---------------------------------------------------------------------------
#define WS_HALVES (12 * 32 * 32 * 4)    // 49152 halves = 98304 B
#define AS_STRIDE 40                    // halves per row
#define AS_STAGE_H (128 * AS_STRIDE)    // 5120 halves = 10240 B
#define SMEM_BYTES (WS_HALVES * 2 + 2 * AS_STAGE_H * 2)  // 118,784 B

__global__ __launch_bounds__(512, 1) void gru_persist(
    float* __restrict__ h0, float* __restrict__ h1,
    const float* __restrict__ W_hh, const float* __restrict__ b_hh,
    const int* __restrict__ tokens)
{
    extern __shared__ __align__(16) char smem8[];
    __half* Ws = (__half*)smem8;                       // frag-ordered W (fp16)
    __half* As = (__half*)(smem8 + WS_HALVES * 2);     // [2][128][40] halves
    float*  Cs = (float*)(smem8 + WS_HALVES * 2);      // epilogue staging

    int tid = threadIdx.x;
    int lane = tid & 31, w = tid >> 5;   // 16 warps
    int g = lane >> 2, tq = lane & 3;
    int kg = w >> 3;                     // k16-half (kt = 2*kt2 + kg)
    int wl = w & 7;
    int m0w = wl >> 1;                   // warp m-band (0..3)
    int m0 = m0w * 32;
    int n0 = (wl & 1) * 48;              // warp col base (0 or 48)
    int n8base = (wl & 1) * 6;
    int rb = blockIdx.y * 128;           // global row base
    int ecb = blockIdx.x * 32;           // global e base
    int cb = ecb * 3;                    // global gate-col base
    int band = blockIdx.y;

    // ---- one-time: build frag-ordered, gate-interleaved fp16 W slice ----
    for (int idx = tid; idx < 96 * 512; idx += 512) {
        int nl = idx >> 9;               // 0..95
        int k = idx & 511;
        int col = cb + nl;               // interleaved gate col
        int e = col / 3, gg = col - 3 * e;
        __half v = __float2half(W_hh[(size_t)(gg * NE + e) * NE + k]);
        int n8 = nl >> 3, bg = nl & 7;
        int kt = k >> 4, kk = k & 15;
        int btq = (kk >> 1) & 3, reg = kk >> 3, hsel = kk & 1;
        Ws[(((n8 * 32 + kt) * 32 + 4 * bg + btq) << 2) + reg * 2 + hsel] = v;
    }
    __syncthreads();

    // A producer mapping: thread (row = tid>>2, q = tid&3) loads two float4
    // per 32-wide pair: cols 4q..+3 and 16+4q..+3, converts to fp16.
    int aRow = tid >> 2, aQ = tid & 3;
    int aOffL = aRow * AS_STRIDE + 4 * aQ;        // halves
    int aOffH = aOffL + 16;

    for (int t = 0; t < NT; t++) {
        const float* hin = (t & 1) ? h1 : h0;
        float* hout      = (t & 1) ? h0 : h1;
        const float* Ag = hin + (size_t)rb * NE;

        // preload pair 0 into stage 0
        {
            float4 a0 = *(const float4*)(Ag + (size_t)aRow * NE + 4 * aQ);
            float4 a1 = *(const float4*)(Ag + (size_t)aRow * NE + 16 + 4 * aQ);
            __half2 p0 = __floats2half2_rn(a0.x, a0.y);
            __half2 p1 = __floats2half2_rn(a0.z, a0.w);
            __half2 p2 = __floats2half2_rn(a1.x, a1.y);
            __half2 p3 = __floats2half2_rn(a1.z, a1.w);
            *(uint2*)(As + aOffL) = make_uint2(h2u(p0), h2u(p1));
            *(uint2*)(As + aOffH) = make_uint2(h2u(p2), h2u(p3));
        }
        __syncthreads();

        float acc[2][6][4];
#pragma unroll
        for (int mi = 0; mi < 2; mi++)
#pragma unroll
            for (int ni = 0; ni < 6; ni++)
#pragma unroll
                for (int j = 0; j < 4; j++) acc[mi][ni][j] = 0.f;

        for (int kt2 = 0; kt2 < 16; kt2++) {
            const __half* Acur = As + (kt2 & 1) * AS_STAGE_H;
            float4 na0, na1;
            if (kt2 < 15) {
                int k0 = (kt2 + 1) * 32;
                na0 = *(const float4*)(Ag + (size_t)aRow * NE + k0 + 4 * aQ);
                na1 = *(const float4*)(Ag + (size_t)aRow * NE + k0 + 16 + 4 * aQ);
            }
            // this warp's k16 tile: kt = 2*kt2 + kg; cols 16*kg of the stage
            {
                int kt = 2 * kt2 + kg;
                unsigned af[2][4];
#pragma unroll
                for (int mi = 0; mi < 2; mi++) {
                    const __half* ap = Acur + (m0 + 16 * mi + g) * AS_STRIDE + 16 * kg + 2 * tq;
                    af[mi][0] = *(const unsigned*)(ap);                    // (g, 2tq)
                    af[mi][1] = *(const unsigned*)(ap + 8 * AS_STRIDE);    // (g+8, 2tq)
                    af[mi][2] = *(const unsigned*)(ap + 8);                // (g, 2tq+8)
                    af[mi][3] = *(const unsigned*)(ap + 8 * AS_STRIDE + 8);
                }
#pragma unroll
                for (int ni = 0; ni < 6; ni++) {
                    uint2 bv = *(const uint2*)(Ws + ((((n8base + ni) * 32 + kt) * 32 + lane) << 2));
                    unsigned bf[2] = { bv.x, bv.y };
                    mma_f16(acc[0][ni], af[0], bf);
                    mma_f16(acc[1][ni], af[1], bf);
                }
            }
            if (kt2 < 15) {
                __half* Anxt = As + ((kt2 + 1) & 1) * AS_STAGE_H;
                __half2 p0 = __floats2half2_rn(na0.x, na0.y);
                __half2 p1 = __floats2half2_rn(na0.z, na0.w);
                __half2 p2 = __floats2half2_rn(na1.x, na1.y);
                __half2 p3 = __floats2half2_rn(na1.z, na1.w);
                *(uint2*)(Anxt + aOffL) = make_uint2(h2u(p0), h2u(p1));
                *(uint2*)(Anxt + aOffH) = make_uint2(h2u(p2), h2u(p3));
            }
            __syncthreads();
        }

        // ---- epilogue: 4 phases of 32 rows; kg0 stores, kg1 adds, gates ----
#pragma unroll
        for (int p = 0; p < 4; p++) {
            if (m0w == p && kg == 0) {
#pragma unroll
                for (int mi = 0; mi < 2; mi++)
#pragma unroll
                    for (int ni = 0; ni < 6; ni++) {
                        int col = n0 + 8 * ni + 2 * tq;
                        *(float2*)&Cs[(16 * mi + g) * 104 + col] =
                            make_float2(acc[mi][ni][0], acc[mi][ni][1]);
                        *(float2*)&Cs[(16 * mi + g + 8) * 104 + col] =
                            make_float2(acc[mi][ni][2], acc[mi][ni][3]);
                    }
            }
            __syncthreads();
            if (m0w == p && kg == 1) {
#pragma unroll
                for (int mi = 0; mi < 2; mi++)
#pragma unroll
                    for (int ni = 0; ni < 6; ni++) {
                        int col = n0 + 8 * ni + 2 * tq;
                        float2* c0 = (float2*)&Cs[(16 * mi + g) * 104 + col];
                        float2 v0 = *c0;
                        v0.x += acc[mi][ni][0]; v0.y += acc[mi][ni][1];
                        *c0 = v0;
                        float2* c1 = (float2*)&Cs[(16 * mi + g + 8) * 104 + col];
                        float2 v1 = *c1;
                        v1.x += acc[mi][ni][2]; v1.y += acc[mi][ni][3];
                        *c1 = v1;
                    }
            }
            __syncthreads();

            for (int i = tid; i < 32 * 32; i += 512) {
                int e = i & 31, r = i >> 5;
                int rg = rb + p * 32 + r;
                int eg = ecb + e;
                float hr = Cs[r * 104 + 3 * e]     + b_hh[eg];
                float hz = Cs[r * 104 + 3 * e + 1] + b_hh[NE + eg];
                float hn = Cs[r * 104 + 3 * e + 2] + b_hh[2 * NE + eg];
                int tok = tokens[rg * NT + t];
                const float* Gr = g_G + (size_t)tok * G3E;
                float ir = Gr[eg], iz = Gr[NE + eg], inn = Gr[2 * NE + eg];
                float rr = fast_sigmoid(ir + hr);
                float zz = fast_sigmoid(iz + hz);
                float nn = fast_tanh(inn + rr * hn);
                float hp = hin[(size_t)rg * NE + eg];
                hout[(size_t)rg * NE + eg] = (1.f - zz) * nn + zz * hp;
            }
            __syncthreads();
        }

        // band's hout writes must land before the band's next step reads them
        band_sync(band);
    }
}

// ---------------------------------------------------------------------------
// Generic tiled GEMM: C[Mr x Nc] = A[Mr x K] * Bm[Nc x K]^T + bias[Nc]
// ---------------------------------------------------------------------------
__global__ __launch_bounds__(256) void gemm64_abT(
    const float* __restrict__ A, const float* __restrict__ Bm,
    const float* __restrict__ bias, float* __restrict__ C, int Nc, int K)
{
    __shared__ float As[64][17];
    __shared__ float Bs[16][65];
    int tid = threadIdx.x;
    int r4 = tid >> 2, q = tid & 3;
    int ty = tid >> 4, tx = tid & 15;
    int rb = blockIdx.y * 64, cb = blockIdx.x * 64;

    float acc[4][4];
#pragma unroll
    for (int i = 0; i < 4; i++)
#pragma unroll
        for (int j = 0; j < 4; j++) acc[i][j] = 0.f;

    for (int k0 = 0; k0 < K; k0 += 16) {
        float4 av = *(const float4*)(A + (size_t)(rb + r4) * K + k0 + q * 4);
        As[r4][q * 4 + 0] = av.x; As[r4][q * 4 + 1] = av.y;
        As[r4][q * 4 + 2] = av.z; As[r4][q * 4 + 3] = av.w;
        float4 bv = *(const float4*)(Bm + (size_t)(cb + r4) * K + k0 + q * 4);
        Bs[q * 4 + 0][r4] = bv.x; Bs[q * 4 + 1][r4] = bv.y;
        Bs[q * 4 + 2][r4] = bv.z; Bs[q * 4 + 3][r4] = bv.w;
        __syncthreads();
#pragma unroll
        for (int kk = 0; kk < 16; kk++) {
            float a[4], b[4];
#pragma unroll
            for (int i = 0; i < 4; i++) a[i] = As[ty * 4 + i][kk];
#pragma unroll
            for (int j = 0; j < 4; j++) b[j] = Bs[kk][tx * 4 + j];
#pragma unroll
            for (int i = 0; i < 4; i++)
#pragma unroll
                for (int j = 0; j < 4; j++) acc[i][j] = fmaf(a[i], b[j], acc[i][j]);
        }
        __syncthreads();
    }
#pragma unroll
    for (int i = 0; i < 4; i++) {
        int row = rb + ty * 4 + i;
#pragma unroll
        for (int j = 0; j < 4; j++) {
            int col = cb + tx * 4 + j;
            C[(size_t)row * Nc + col] = acc[i][j] + bias[col];
        }
    }
}

__global__ void init_kernel(float* h0)
{
    int i = blockIdx.x * blockDim.x + threadIdx.x;
    if (i < NB * NE) h0[i] = 0.f;
    if (i < 8) { g_barCount[i] = 0u; g_barGen[i] = 0u; }
}

// ---------------------------------------------------------------------------
// psi init: split zc -> (re, im), complex_normalize per row.
// ---------------------------------------------------------------------------
__global__ __launch_bounds__(256) void psi_init_kernel()
{
    int b = blockIdx.x, tid = threadIdx.x;
    __shared__ float red[8];
    const float* zrow = g_zc + (size_t)b * 2 * NM;
    float ss = 0.f;
    for (int m = tid; m < NM; m += 256) {
        float re = zrow[m], im = zrow[NM + m];
        ss += re * re + im * im;
    }
    for (int o = 16; o; o >>= 1) ss += __shfl_xor_sync(0xffffffffu, ss, o);
    if ((tid & 31) == 0) red[tid >> 5] = ss;
    __syncthreads();
    if (tid < 8) {
        float v = red[tid];
        for (int o = 4; o; o >>= 1) v += __shfl_xor_sync(0xffu, v, o);
        if (tid == 0) red[0] = v;
    }
    __syncthreads();
    float inv = rsqrtf(red[0] + 1e-8f);
    for (int m = tid; m < NM; m += 256) {
        g_pr[(size_t)b * NM + m] = zrow[m] * inv;
        g_pi[(size_t)b * NM + m] = zrow[NM + m] * inv;
    }
}

// ---------------------------------------------------------------------------
// MZI layers: one block per batch row, psi row lives in SMEM for all 32 layers.
// ---------------------------------------------------------------------------
__device__ __forceinline__ void pair_apply(int a, int c, float tt, float pp, float rr,
                                           float* sre, float* sim)
{
    float st, ct; __sincosf(tt, &st, &ct);
    float sp, cp; __sincosf(pp, &sp, &cp);
    float sr, cr; __sincosf(rr, &sr, &cr);
    float cpr = cp * cr - sp * sr;
    float spr = sp * cr + cp * sr;
    float u11r = ct * cpr, u11i = ct * spr;
    float u12r = -st * sp, u12i = st * cp;
    float u21r = -st * sr, u21i = st * cr;
    float u22  = ct;
    float v0r = sre[a], v0i = sim[a], v1r = sre[c], v1i = sim[c];
    float n0r = u11r * v0r - u11i * v0i + u12r * v1r - u12i * v1i;
    float n0i = u11r * v0i + u11i * v0r + u12r * v1i + u12i * v1r;
    float n1r = u21r * v0r - u21i * v0i + u22 * v1r;
    float n1i = u21r * v0i + u21i * v0r + u22 * v1i;
    sre[a] = n0r; sim[a] = n0i; sre[c] = n1r; sim[c] = n1i;
}

__global__ __launch_bounds__(512) void mzi_kernel(
    const float* __restrict__ phase, const float* __restrict__ te,
    const float* __restrict__ pe, const float* __restrict__ re_,
    const float* __restrict__ to, const float* __restrict__ po,
    const float* __restrict__ ro)
{
    __shared__ float sre[NM], sim[NM];
    __shared__ float red[16];
    int b = blockIdx.x, tid = threadIdx.x;
    sre[tid] = g_pr[(size_t)b * NM + tid];
    sre[tid + 512] = g_pr[(size_t)b * NM + tid + 512];
    sim[tid] = g_pi[(size_t)b * NM + tid];
    sim[tid + 512] = g_pi[(size_t)b * NM + tid + 512];
    __syncthreads();

    for (int l = 0; l < NL; l++) {
#pragma unroll
        for (int h = 0; h < 2; h++) {
            int mm = tid + h * 512;
            float s, c; __sincosf(phase[l * NM + mm], &s, &c);
            float r0 = sre[mm], i0 = sim[mm];
            sre[mm] = r0 * c - i0 * s;
            sim[mm] = r0 * s + i0 * c;
        }
        __syncthreads();
        pair_apply(2 * tid, 2 * tid + 1,
                   te[l * NPE + tid], pe[l * NPE + tid], re_[l * NPE + tid], sre, sim);
        __syncthreads();
        if (tid < NPO)
            pair_apply(2 * tid + 1, 2 * tid + 2,
                       to[l * NPO + tid], po[l * NPO + tid], ro[l * NPO + tid], sre, sim);
        __syncthreads();
        float ss = sre[tid] * sre[tid] + sim[tid] * sim[tid]
                 + sre[tid + 512] * sre[tid + 512] + sim[tid + 512] * sim[tid + 512];
        for (int o = 16; o; o >>= 1) ss += __shfl_xor_sync(0xffffffffu, ss, o);
        if ((tid & 31) == 0) red[tid >> 5] = ss;
        __syncthreads();
        if (tid < 16) {
            float v = red[tid];
            for (int o = 8; o; o >>= 1) v += __shfl_xor_sync(0xffffu, v, o);
            if (tid == 0) red[0] = v;
        }
        __syncthreads();
        float inv = rsqrtf(red[0] + 1e-8f);
        sre[tid] *= inv; sim[tid] *= inv;
        sre[tid + 512] *= inv; sim[tid + 512] *= inv;
        __syncthreads();
    }

    g_pr[(size_t)b * NM + tid] = sre[tid];
    g_pr[(size_t)b * NM + tid + 512] = sre[tid + 512];
    g_pi[(size_t)b * NM + tid] = sim[tid];
    g_pi[(size_t)b * NM + tid + 512] = sim[tid + 512];
}

// ---------------------------------------------------------------------------
// Readout: amps = psi @ R^T (complex), out = log(|amps|^2 + 1e-12).
// ---------------------------------------------------------------------------
__global__ __launch_bounds__(256) void readout_kernel(
    const float* __restrict__ Rr, const float* __restrict__ Ri,
    float* __restrict__ out)
{
    __shared__ float Ar[64][17], Ai[64][17];
    __shared__ float Br[16][65], Bi[16][65];
    int tid = threadIdx.x;
    int r4 = tid >> 2, q = tid & 3;
    int ty = tid >> 4, tx = tid & 15;
    int rb = blockIdx.y * 64, cb = blockIdx.x * 64;

    float accr[4][4], acci[4][4];
#pragma unroll
    for (int i = 0; i < 4; i++)
#pragma unroll
        for (int j = 0; j < 4; j++) { accr[i][j] = 0.f; acci[i][j] = 0.f; }

    for (int k0 = 0; k0 < NM; k0 += 16) {
        float4 v;
        v = *(const float4*)(g_pr + (size_t)(rb + r4) * NM + k0 + q * 4);
        Ar[r4][q * 4 + 0] = v.x; Ar[r4][q * 4 + 1] = v.y;
        Ar[r4][q * 4 + 2] = v.z; Ar[r4][q * 4 + 3] = v.w;
        v = *(const float4*)(g_pi + (size_t)(rb + r4) * NM + k0 + q * 4);
        Ai[r4][q * 4 + 0] = v.x; Ai[r4][q * 4 + 1] = v.y;
        Ai[r4][q * 4 + 2] = v.z; Ai[r4][q * 4 + 3] = v.w;
        v = *(const float4*)(Rr + (size_t)(cb + r4) * NM + k0 + q * 4);
        Br[q * 4 + 0][r4] = v.x; Br[q * 4 + 1][r4] = v.y;
        Br[q * 4 + 2][r4] = v.z; Br[q * 4 + 3][r4] = v.w;
        v = *(const float4*)(Ri + (size_t)(cb + r4) * NM + k0 + q * 4);
        Bi[q * 4 + 0][r4] = v.x; Bi[q * 4 + 1][r4] = v.y;
        Bi[q * 4 + 2][r4] = v.z; Bi[q * 4 + 3][r4] = v.w;
        __syncthreads();
#pragma unroll
        for (int kk = 0; kk < 16; kk++) {
            float par[4], pai[4], wbr[4], wbi[4];
#pragma unroll
            for (int i = 0; i < 4; i++) { par[i] = Ar[ty * 4 + i][kk]; pai[i] = Ai[ty * 4 + i][kk]; }
#pragma unroll
            for (int j = 0; j < 4; j++) { wbr[j] = Br[kk][tx * 4 + j]; wbi[j] = Bi[kk][tx * 4 + j]; }
#pragma unroll
            for (int i = 0; i < 4; i++)
#pragma unroll
                for (int j = 0; j < 4; j++) {
                    accr[i][j] = fmaf(par[i], wbr[j], accr[i][j]);
                    accr[i][j] = fmaf(-pai[i], wbi[j], accr[i][j]);
                    acci[i][j] = fmaf(par[i], wbi[j], acci[i][j]);
                    acci[i][j] = fmaf(pai[i], wbr[j], acci[i][j]);
                }
        }
        __syncthreads();
    }
#pragma unroll
    for (int i = 0; i < 4; i++) {
        int row = rb + ty * 4 + i;
#pragma unroll
        for (int j = 0; j < 4; j++) {
            int col = cb + tx * 4 + j;
            float ar = accr[i][j], ai = acci[i][j];
            out[(size_t)row * NV + col] = __logf(ar * ar + ai * ai + 1e-12f);
        }
    }
}

// ---------------------------------------------------------------------------
// Row-wise logsumexp, subtract in place.
// ---------------------------------------------------------------------------
__global__ __launch_bounds__(256) void lse_kernel(float* __restrict__ out)
{
    int b = blockIdx.x, tid = threadIdx.x;
    __shared__ float red[8];
    float* row = out + (size_t)b * NV;

    float mx = -INFINITY;
    for (int v = tid; v < NV; v += 256) mx = fmaxf(mx, row[v]);
    for (int o = 16; o; o >>= 1) mx = fmaxf(mx, __shfl_xor_sync(0xffffffffu, mx, o));
    if ((tid & 31) == 0) red[tid >> 5] = mx;
    __syncthreads();
    if (tid < 8) {
        float v = red[tid];
        for (int o = 4; o; o >>= 1) v = fmaxf(v, __shfl_xor_sync(0xffu, v, o));
        if (tid == 0) red[0] = v;
    }
    __syncthreads();
    mx = red[0];
    __syncthreads();

    float se = 0.f;
    for (int v = tid; v < NV; v += 256) se += __expf(row[v] - mx);
    for (int o = 16; o; o >>= 1) se += __shfl_xor_sync(0xffffffffu, se, o);
    if ((tid & 31) == 0) red[tid >> 5] = se;
    __syncthreads();
    if (tid < 8) {
        float v = red[tid];
        for (int o = 4; o; o >>= 1) v += __shfl_xor_sync(0xffu, v, o);
        if (tid == 0) red[0] = v;
    }
    __syncthreads();
    float lse = mx + __logf(red[0]);
    for (int v = tid; v < NV; v += 256) row[v] -= lse;
}

// ---------------------------------------------------------------------------
extern "C" void kernel_launch(void* const* d_in, const int* in_sizes, int n_in,
                              void* d_out, int out_size)
{
    const int*   tokens = (const int*)d_in[0];
    const float* embed  = (const float*)d_in[1];
    const float* W_ih   = (const float*)d_in[2];
    const float* W_hh   = (const float*)d_in[3];
    const float* b_ih   = (const float*)d_in[4];
    const float* b_hh   = (const float*)d_in[5];
    const float* Wc     = (const float*)d_in[6];
    const float* bc     = (const float*)d_in[7];
    const float* phase  = (const float*)d_in[8];
    const float* te     = (const float*)d_in[9];
    const float* pe     = (const float*)d_in[10];
    const float* re_    = (const float*)d_in[11];
    const float* to     = (const float*)d_in[12];
    const float* po     = (const float*)d_in[13];
    const float* ro     = (const float*)d_in[14];
    const float* Rr     = (const float*)d_in[15];
    const float* Ri     = (const float*)d_in[16];
    float* out = (float*)d_out;

    static float* pG = nullptr;
    static float* pH = nullptr;
    static float* pZC = nullptr;
    if (!pG) {
        cudaGetSymbolAddress((void**)&pG, g_G);
        cudaGetSymbolAddress((void**)&pH, g_h);
        cudaGetSymbolAddress((void**)&pZC, g_zc);
        cudaFuncSetAttribute(gru_persist,
                             cudaFuncAttributeMaxDynamicSharedMemorySize, SMEM_BYTES);
    }
    float* pH0 = pH;
    float* pH1 = pH + NB * NE;

    // 1. Token gate table: G = embed @ W_ih^T + b_ih  (V x 3E)
    gemm64_abT<<<dim3(G3E / 64, NV / 64), 256>>>(embed, W_ih, b_ih, pG, G3E, NE);

    // 2. h0 = 0 + barrier state reset
    init_kernel<<<(NB * NE + 255) / 256, 256>>>(pH0);

    // 3. Whole GRU recurrence in ONE persistent kernel (fp16 mma, K-split)
    gru_persist<<<dim3(16, 8), 512, SMEM_BYTES>>>(pH0, pH1, W_hh, b_hh, tokens);

    // 4. zc = h @ Wc^T + bc, then normalized complex psi (NT even -> h in pH0)
    gemm64_abT<<<dim3(2 * NM / 64, NB / 64), 256>>>(pH0, Wc, bc, pZC, 2 * NM, NE);
    psi_init_kernel<<<NB, 256>>>();

    // 5. 32 MZI layers, persistent row in SMEM
    mzi_kernel<<<NB, 512>>>(phase, te, pe, re_, to, po, ro);

    // 6. Readout complex GEMM + log|.|^2, then row logsumexp
    readout_kernel<<<dim3(NV / 64, NB / 64), 256>>>(Rr, Ri, out);
    lse_kernel<<<NB, 256>>>(out);
}

// round 14
// speedup vs baseline: 1.8105x; 1.0533x over previous
#include <cuda_runtime.h>
#include <cuda_fp16.h>
#include <math.h>
#include <string.h>

// Problem dims
#define NB 1024   // batch
#define NT 64     // time steps
#define NV 1024   // vocab
#define NE 512    // embed dim
#define NM 1024   // modes
#define NL 32     // MZI layers
#define NPE 512   // even pairs
#define NPO 511   // odd pairs
#define G3E 1536  // 3*NE

// Scratch (no allocations allowed -> __device__ globals)
__device__ float g_G[NV * G3E];       // token gate table: embed@W_ih^T + b_ih
__device__ float g_h[2][NB * NE];     // GRU hidden double buffer
__device__ float g_zc[NB * 2 * NM];   // h@Wc^T + bc
__device__ float g_pr[NB * NM];       // psi real
__device__ float g_pi[NB * NM];       // psi imag
__device__ unsigned g_barCount[8];    // per-band barrier state
__device__ unsigned g_barGen[8];

// ---------------------------------------------------------------------------
// fp16 helpers
// ---------------------------------------------------------------------------
__device__ __forceinline__ unsigned h2u(__half2 h) {
    unsigned u;
    memcpy(&u, &h, 4);
    return u;
}

__device__ __forceinline__ void mma_f16(float* c, const unsigned* a, const unsigned* b) {
    asm("mma.sync.aligned.m16n8k16.row.col.f32.f16.f16.f32 "
        "{%0,%1,%2,%3}, {%4,%5,%6,%7}, {%8,%9}, {%0,%1,%2,%3};"
        : "+f"(c[0]), "+f"(c[1]), "+f"(c[2]), "+f"(c[3])
        : "r"(a[0]), "r"(a[1]), "r"(a[2]), "r"(a[3]), "r"(b[0]), "r"(b[1]));
}

__device__ __forceinline__ float fast_sigmoid(float x) {
    return 1.f / (1.f + __expf(-x));
}
__device__ __forceinline__ float fast_tanh(float x) {
    x = fminf(15.f, fmaxf(-15.f, x));
    float e2 = __expf(2.f * x);
    return (e2 - 1.f) / (e2 + 1.f);
}

// ---------------------------------------------------------------------------
// Per-band grid barrier: the GRU recurrence only couples the 16 CTAs that
// share blockIdx.y. All 128 CTAs are wave-1 resident (1 CTA/SM).
// ---------------------------------------------------------------------------
#define NCTA_BAND 16
__device__ __forceinline__ void band_sync(int band)
{
    __threadfence();
    __syncthreads();
    if (threadIdx.x == 0) {
        unsigned gen = *(volatile unsigned*)&g_barGen[band];
        if (atomicAdd(&g_barCount[band], 1u) == NCTA_BAND - 1) {
            g_barCount[band] = 0;
            __threadfence();
            atomicExch(&g_barGen[band], gen + 1u);
        } else {
            while (*(volatile unsigned*)&g_barGen[band] == gen) { __nanosleep(32); }
            __threadfence();
        }
    }
    __syncthreads();
}

// ---------------------------------------------------------------------------
// Persistent GRU, fp16 m16n8k16, 512 threads (16 warps), K-split by k16-tile
// parity. Wide 128-col A stages -> only 4 mainloop syncs per step.
//
// CTA tile: 128 batch rows x 96 gate cols (32 hidden units, gates interleaved
// e*3+g). Warp (kg, m, n): kg = w>>3 computes tiles tl with (tl&1)==kg of
// each 8-tile stage; m=(w>>1)&3 -> 32-row band; n=w&1 -> 48-col band.
//
// W resident all 64 steps, fp16 B-fragment order (R12-proven):
//   [n8:12][kt:32][lane:32][4 halves] -> one LDS.64 per frag, conflict-free.
// A staged row-major fp16, 128 cols/stage, stride 136 halves (68 words,
// 68%32==4): frag LDS.32 banks = 4g + 8*tl + tq -> conflict-free.
// ---------------------------------------------------------------------------
#define WS_HALVES (12 * 32 * 32 * 4)    // 49152 halves = 98304 B
#define AS_STRIDE 136                   // halves per row
#define AS_STAGE_H (128 * AS_STRIDE)    // 17408 halves = 34816 B
#define SMEM_BYTES (WS_HALVES * 2 + 2 * AS_STAGE_H * 2)  // 167,936 B

__global__ __launch_bounds__(512, 1) void gru_persist(
    float* __restrict__ h0, float* __restrict__ h1,
    const float* __restrict__ W_hh, const float* __restrict__ b_hh,
    const int* __restrict__ tokens)
{
    extern __shared__ __align__(16) char smem8[];
    __half* Ws = (__half*)smem8;                       // frag-ordered W (fp16)
    __half* As = (__half*)(smem8 + WS_HALVES * 2);     // [2][128][136] halves
    float*  Cs = (float*)(smem8 + WS_HALVES * 2);      // epilogue staging

    int tid = threadIdx.x;
    int lane = tid & 31, w = tid >> 5;   // 16 warps
    int g = lane >> 2, tq = lane & 3;
    int kg = w >> 3;                     // tile parity handled by this warp
    int wl = w & 7;
    int m0w = wl >> 1;                   // warp m-band (0..3)
    int m0 = m0w * 32;
    int n0 = (wl & 1) * 48;              // warp col base (0 or 48)
    int n8base = (wl & 1) * 6;
    int rb = blockIdx.y * 128;           // global row base
    int ecb = blockIdx.x * 32;           // global e base
    int cb = ecb * 3;                    // global gate-col base
    int band = blockIdx.y;

    // ---- one-time: build frag-ordered, gate-interleaved fp16 W slice ----
    for (int idx = tid; idx < 96 * 512; idx += 512) {
        int nl = idx >> 9;               // 0..95
        int k = idx & 511;
        int col = cb + nl;               // interleaved gate col
        int e = col / 3, gg = col - 3 * e;
        __half v = __float2half(W_hh[(size_t)(gg * NE + e) * NE + k]);
        int n8 = nl >> 3, bg = nl & 7;
        int kt = k >> 4, kk = k & 15;
        int btq = (kk >> 1) & 3, reg = kk >> 3, hsel = kk & 1;
        Ws[(((n8 * 32 + kt) * 32 + 4 * bg + btq) << 2) + reg * 2 + hsel] = v;
    }
    __syncthreads();

    // A producer: thread (row = tid>>2, cq = tid&3); per 128-col stage loads
    // 8 float4 at cols 16j + 4cq, stores as half2-pairs (uint2 = 4 halves).
    int aRow = tid >> 2, cq = tid & 3;
    const size_t aRowOff = (size_t)aRow * NE;
    int sBase = aRow * AS_STRIDE + 4 * cq;   // halves

    for (int t = 0; t < NT; t++) {
        const float* hin = (t & 1) ? h1 : h0;
        float* hout      = (t & 1) ? h0 : h1;
        const float* Ag = hin + (size_t)rb * NE;

        // preload stage 0 (cols 0..127)
        {
#pragma unroll
            for (int j = 0; j < 8; j++) {
                float4 a = *(const float4*)(Ag + aRowOff + 16 * j + 4 * cq);
                uint2 u = make_uint2(h2u(__floats2half2_rn(a.x, a.y)),
                                     h2u(__floats2half2_rn(a.z, a.w)));
                *(uint2*)(As + sBase + 16 * j) = u;
            }
        }
        __syncthreads();

        float acc[2][6][4];
#pragma unroll
        for (int mi = 0; mi < 2; mi++)
#pragma unroll
            for (int ni = 0; ni < 6; ni++)
#pragma unroll
                for (int j = 0; j < 4; j++) acc[mi][ni][j] = 0.f;

        for (int ot = 0; ot < 4; ot++) {
            const __half* Acur = As + (ot & 1) * AS_STAGE_H;
            // prefetch next stage into registers (converted to half2 pairs)
            uint2 pre[8];
            if (ot < 3) {
                int c0 = (ot + 1) * 128;
#pragma unroll
                for (int j = 0; j < 8; j++) {
                    float4 a = *(const float4*)(Ag + aRowOff + c0 + 16 * j + 4 * cq);
                    pre[j] = make_uint2(h2u(__floats2half2_rn(a.x, a.y)),
                                        h2u(__floats2half2_rn(a.z, a.w)));
                }
            }
            // compute this warp's 4 tiles of the stage: tl = 2*j2 + kg
#pragma unroll
            for (int j2 = 0; j2 < 4; j2++) {
                int tl = 2 * j2 + kg;            // tile within stage (0..7)
                int kt = 8 * ot + tl;            // global k16 tile
                unsigned af[2][4];
#pragma unroll
                for (int mi = 0; mi < 2; mi++) {
                    const __half* ap = Acur + (m0 + 16 * mi + g) * AS_STRIDE + 16 * tl + 2 * tq;
                    af[mi][0] = *(const unsigned*)(ap);
                    af[mi][1] = *(const unsigned*)(ap + 8 * AS_STRIDE);
                    af[mi][2] = *(const unsigned*)(ap + 8);
                    af[mi][3] = *(const unsigned*)(ap + 8 * AS_STRIDE + 8);
                }
#pragma unroll
                for (int ni = 0; ni < 6; ni++) {
                    uint2 bv = *(const uint2*)(Ws + ((((n8base + ni) * 32 + kt) * 32 + lane) << 2));
                    unsigned bf[2] = { bv.x, bv.y };
                    mma_f16(acc[0][ni], af[0], bf);
                    mma_f16(acc[1][ni], af[1], bf);
                }
            }
            if (ot < 3) {
                __half* Anxt = As + ((ot + 1) & 1) * AS_STAGE_H;
#pragma unroll
                for (int j = 0; j < 8; j++)
                    *(uint2*)(Anxt + sBase + 16 * j) = pre[j];
            }
            __syncthreads();
        }

        // ---- epilogue: 4 phases of 32 rows; kg0 stores, kg1 adds, gates ----
#pragma unroll
        for (int p = 0; p < 4; p++) {
            if (m0w == p && kg == 0) {
#pragma unroll
                for (int mi = 0; mi < 2; mi++)
#pragma unroll
                    for (int ni = 0; ni < 6; ni++) {
                        int col = n0 + 8 * ni + 2 * tq;
                        *(float2*)&Cs[(16 * mi + g) * 104 + col] =
                            make_float2(acc[mi][ni][0], acc[mi][ni][1]);
                        *(float2*)&Cs[(16 * mi + g + 8) * 104 + col] =
                            make_float2(acc[mi][ni][2], acc[mi][ni][3]);
                    }
            }
            __syncthreads();
            if (m0w == p && kg == 1) {
#pragma unroll
                for (int mi = 0; mi < 2; mi++)
#pragma unroll
                    for (int ni = 0; ni < 6; ni++) {
                        int col = n0 + 8 * ni + 2 * tq;
                        float2* c0 = (float2*)&Cs[(16 * mi + g) * 104 + col];
                        float2 v0 = *c0;
                        v0.x += acc[mi][ni][0]; v0.y += acc[mi][ni][1];
                        *c0 = v0;
                        float2* c1 = (float2*)&Cs[(16 * mi + g + 8) * 104 + col];
                        float2 v1 = *c1;
                        v1.x += acc[mi][ni][2]; v1.y += acc[mi][ni][3];
                        *c1 = v1;
                    }
            }
            __syncthreads();

            for (int i = tid; i < 32 * 32; i += 512) {
                int e = i & 31, r = i >> 5;
                int rg = rb + p * 32 + r;
                int eg = ecb + e;
                float hr = Cs[r * 104 + 3 * e]     + b_hh[eg];
                float hz = Cs[r * 104 + 3 * e + 1] + b_hh[NE + eg];
                float hn = Cs[r * 104 + 3 * e + 2] + b_hh[2 * NE + eg];
                int tok = tokens[rg * NT + t];
                const float* Gr = g_G + (size_t)tok * G3E;
                float ir = Gr[eg], iz = Gr[NE + eg], inn = Gr[2 * NE + eg];
                float rr = fast_sigmoid(ir + hr);
                float zz = fast_sigmoid(iz + hz);
                float nn = fast_tanh(inn + rr * hn);
                float hp = hin[(size_t)rg * NE + eg];
                hout[(size_t)rg * NE + eg] = (1.f - zz) * nn + zz * hp;
            }
            __syncthreads();
        }

        // band's hout writes must land before the band's next step reads them
        band_sync(band);
    }
}

// ---------------------------------------------------------------------------
// Tiled GEMM: C[Mr x Nc] = A[Mr x K] * Bm[Nc x K]^T + bias[Nc]
// BM=128, BN=64, BK=16, 256 threads, 8x4 microtile (32 FMA / 12 LDS).
// Mr must be a multiple of 128; Nc of 64; K of 16.
// ---------------------------------------------------------------------------
__global__ __launch_bounds__(256) void gemm128_abT(
    const float* __restrict__ A, const float* __restrict__ Bm,
    const float* __restrict__ bias, float* __restrict__ C, int Nc, int K)
{
    __shared__ float As[128][17];
    __shared__ float Bs[16][65];
    int tid = threadIdx.x;
    int q = tid & 3;
    int aRow0 = tid >> 2, aRow1 = 64 + (tid >> 2);
    int ty = tid >> 4, tx = tid & 15;
    int rb = blockIdx.y * 128, cb = blockIdx.x * 64;

    float acc[8][4];
#pragma unroll
    for (int i = 0; i < 8; i++)
#pragma unroll
        for (int j = 0; j < 4; j++) acc[i][j] = 0.f;

    for (int k0 = 0; k0 < K; k0 += 16) {
        float4 av0 = *(const float4*)(A + (size_t)(rb + aRow0) * K + k0 + q * 4);
        float4 av1 = *(const float4*)(A + (size_t)(rb + aRow1) * K + k0 + q * 4);
        As[aRow0][q * 4 + 0] = av0.x; As[aRow0][q * 4 + 1] = av0.y;
        As[aRow0][q * 4 + 2] = av0.z; As[aRow0][q * 4 + 3] = av0.w;
        As[aRow1][q * 4 + 0] = av1.x; As[aRow1][q * 4 + 1] = av1.y;
        As[aRow1][q * 4 + 2] = av1.z; As[aRow1][q * 4 + 3] = av1.w;
        float4 bv = *(const float4*)(Bm + (size_t)(cb + aRow0) * K + k0 + q * 4);
        Bs[q * 4 + 0][aRow0] = bv.x; Bs[q * 4 + 1][aRow0] = bv.y;
        Bs[q * 4 + 2][aRow0] = bv.z; Bs[q * 4 + 3][aRow0] = bv.w;
        __syncthreads();
#pragma unroll
        for (int kk = 0; kk < 16; kk++) {
            float a[8], b[4];
#pragma unroll
            for (int i = 0; i < 8; i++) a[i] = As[ty * 8 + i][kk];
#pragma unroll
            for (int j = 0; j < 4; j++) b[j] = Bs[kk][tx * 4 + j];
#pragma unroll
            for (int i = 0; i < 8; i++)
#pragma unroll
                for (int j = 0; j < 4; j++) acc[i][j] = fmaf(a[i], b[j], acc[i][j]);
        }
        __syncthreads();
    }
#pragma unroll
    for (int i = 0; i < 8; i++) {
        int row = rb + ty * 8 + i;
#pragma unroll
        for (int j = 0; j < 4; j++) {
            int col = cb + tx * 4 + j;
            C[(size_t)row * Nc + col] = acc[i][j] + bias[col];
        }
    }
}

__global__ void init_kernel(float* h0)
{
    int i = blockIdx.x * blockDim.x + threadIdx.x;
    if (i < NB * NE) h0[i] = 0.f;
    if (i < 8) { g_barCount[i] = 0u; g_barGen[i] = 0u; }
}

// ---------------------------------------------------------------------------
// psi init: split zc -> (re, im), complex_normalize per row.
// ---------------------------------------------------------------------------
__global__ __launch_bounds__(256) void psi_init_kernel()
{
    int b = blockIdx.x, tid = threadIdx.x;
    __shared__ float red[8];
    const float* zrow = g_zc + (size_t)b * 2 * NM;
    float ss = 0.f;
    for (int m = tid; m < NM; m += 256) {
        float re = zrow[m], im = zrow[NM + m];
        ss += re * re + im * im;
    }
    for (int o = 16; o; o >>= 1) ss += __shfl_xor_sync(0xffffffffu, ss, o);
    if ((tid & 31) == 0) red[tid >> 5] = ss;
    __syncthreads();
    if (tid < 8) {
        float v = red[tid];
        for (int o = 4; o; o >>= 1) v += __shfl_xor_sync(0xffu, v, o);
        if (tid == 0) red[0] = v;
    }
    __syncthreads();
    float inv = rsqrtf(red[0] + 1e-8f);
    for (int m = tid; m < NM; m += 256) {
        g_pr[(size_t)b * NM + m] = zrow[m] * inv;
        g_pi[(size_t)b * NM + m] = zrow[NM + m] * inv;
    }
}

// ---------------------------------------------------------------------------
// MZI layers: one block per batch row, psi row lives in SMEM for all 32 layers.
// ---------------------------------------------------------------------------
__device__ __forceinline__ void pair_apply(int a, int c, float tt, float pp, float rr,
                                           float* sre, float* sim)
{
    float st, ct; __sincosf(tt, &st, &ct);
    float sp, cp; __sincosf(pp, &sp, &cp);
    float sr, cr; __sincosf(rr, &sr, &cr);
    float cpr = cp * cr - sp * sr;
    float spr = sp * cr + cp * sr;
    float u11r = ct * cpr, u11i = ct * spr;
    float u12r = -st * sp, u12i = st * cp;
    float u21r = -st * sr, u21i = st * cr;
    float u22  = ct;
    float v0r = sre[a], v0i = sim[a], v1r = sre[c], v1i = sim[c];
    float n0r = u11r * v0r - u11i * v0i + u12r * v1r - u12i * v1i;
    float n0i = u11r * v0i + u11i * v0r + u12r * v1i + u12i * v1r;
    float n1r = u21r * v0r - u21i * v0i + u22 * v1r;
    float n1i = u21r * v0i + u21i * v0r + u22 * v1i;
    sre[a] = n0r; sim[a] = n0i; sre[c] = n1r; sim[c] = n1i;
}

__global__ __launch_bounds__(512) void mzi_kernel(
    const float* __restrict__ phase, const float* __restrict__ te,
    const float* __restrict__ pe, const float* __restrict__ re_,
    const float* __restrict__ to, const float* __restrict__ po,
    const float* __restrict__ ro)
{
    __shared__ float sre[NM], sim[NM];
    __shared__ float red[16];
    int b = blockIdx.x, tid = threadIdx.x;
    sre[tid] = g_pr[(size_t)b * NM + tid];
    sre[tid + 512] = g_pr[(size_t)b * NM + tid + 512];
    sim[tid] = g_pi[(size_t)b * NM + tid];
    sim[tid + 512] = g_pi[(size_t)b * NM + tid + 512];
    __syncthreads();

    for (int l = 0; l < NL; l++) {
#pragma unroll
        for (int h = 0; h < 2; h++) {
            int mm = tid + h * 512;
            float s, c; __sincosf(phase[l * NM + mm], &s, &c);
            float r0 = sre[mm], i0 = sim[mm];
            sre[mm] = r0 * c - i0 * s;
            sim[mm] = r0 * s + i0 * c;
        }
        __syncthreads();
        pair_apply(2 * tid, 2 * tid + 1,
                   te[l * NPE + tid], pe[l * NPE + tid], re_[l * NPE + tid], sre, sim);
        __syncthreads();
        if (tid < NPO)
            pair_apply(2 * tid + 1, 2 * tid + 2,
                       to[l * NPO + tid], po[l * NPO + tid], ro[l * NPO + tid], sre, sim);
        __syncthreads();
        float ss = sre[tid] * sre[tid] + sim[tid] * sim[tid]
                 + sre[tid + 512] * sre[tid + 512] + sim[tid + 512] * sim[tid + 512];
        for (int o = 16; o; o >>= 1) ss += __shfl_xor_sync(0xffffffffu, ss, o);
        if ((tid & 31) == 0) red[tid >> 5] = ss;
        __syncthreads();
        if (tid < 16) {
            float v = red[tid];
            for (int o = 8; o; o >>= 1) v += __shfl_xor_sync(0xffffu, v, o);
            if (tid == 0) red[0] = v;
        }
        __syncthreads();
        float inv = rsqrtf(red[0] + 1e-8f);
        sre[tid] *= inv; sim[tid] *= inv;
        sre[tid + 512] *= inv; sim[tid + 512] *= inv;
        __syncthreads();
    }

    g_pr[(size_t)b * NM + tid] = sre[tid];
    g_pr[(size_t)b * NM + tid + 512] = sre[tid + 512];
    g_pi[(size_t)b * NM + tid] = sim[tid];
    g_pi[(size_t)b * NM + tid + 512] = sim[tid + 512];
}

// ---------------------------------------------------------------------------
// Readout: amps = psi @ R^T (complex), out = log(|amps|^2 + 1e-12).
// ---------------------------------------------------------------------------
__global__ __launch_bounds__(256) void readout_kernel(
    const float* __restrict__ Rr, const float* __restrict__ Ri,
    float* __restrict__ out)
{
    __shared__ float Ar[64][17], Ai[64][17];
    __shared__ float Br[16][65], Bi[16][65];
    int tid = threadIdx.x;
    int r4 = tid >> 2, q = tid & 3;
    int ty = tid >> 4, tx = tid & 15;
    int rb = blockIdx.y * 64, cb = blockIdx.x * 64;

    float accr[4][4], acci[4][4];
#pragma unroll
    for (int i = 0; i < 4; i++)
#pragma unroll
        for (int j = 0; j < 4; j++) { accr[i][j] = 0.f; acci[i][j] = 0.f; }

    for (int k0 = 0; k0 < NM; k0 += 16) {
        float4 v;
        v = *(const float4*)(g_pr + (size_t)(rb + r4) * NM + k0 + q * 4);
        Ar[r4][q * 4 + 0] = v.x; Ar[r4][q * 4 + 1] = v.y;
        Ar[r4][q * 4 + 2] = v.z; Ar[r4][q * 4 + 3] = v.w;
        v = *(const float4*)(g_pi + (size_t)(rb + r4) * NM + k0 + q * 4);
        Ai[r4][q * 4 + 0] = v.x; Ai[r4][q * 4 + 1] = v.y;
        Ai[r4][q * 4 + 2] = v.z; Ai[r4][q * 4 + 3] = v.w;
        v = *(const float4*)(Rr + (size_t)(cb + r4) * NM + k0 + q * 4);
        Br[q * 4 + 0][r4] = v.x; Br[q * 4 + 1][r4] = v.y;
        Br[q * 4 + 2][r4] = v.z; Br[q * 4 + 3][r4] = v.w;
        v = *(const float4*)(Ri + (size_t)(cb + r4) * NM + k0 + q * 4);
        Bi[q * 4 + 0][r4] = v.x; Bi[q * 4 + 1][r4] = v.y;
        Bi[q * 4 + 2][r4] = v.z; Bi[q * 4 + 3][r4] = v.w;
        __syncthreads();
#pragma unroll
        for (int kk = 0; kk < 16; kk++) {
            float par[4], pai[4], wbr[4], wbi[4];
#pragma unroll
            for (int i = 0; i < 4; i++) { par[i] = Ar[ty * 4 + i][kk]; pai[i] = Ai[ty * 4 + i][kk]; }
#pragma unroll
            for (int j = 0; j < 4; j++) { wbr[j] = Br[kk][tx * 4 + j]; wbi[j] = Bi[kk][tx * 4 + j]; }
#pragma unroll
            for (int i = 0; i < 4; i++)
#pragma unroll
                for (int j = 0; j < 4; j++) {
                    accr[i][j] = fmaf(par[i], wbr[j], accr[i][j]);
                    accr[i][j] = fmaf(-pai[i], wbi[j], accr[i][j]);
                    acci[i][j] = fmaf(par[i], wbi[j], acci[i][j]);
                    acci[i][j] = fmaf(pai[i], wbr[j], acci[i][j]);
                }
        }
        __syncthreads();
    }
#pragma unroll
    for (int i = 0; i < 4; i++) {
        int row = rb + ty * 4 + i;
#pragma unroll
        for (int j = 0; j < 4; j++) {
            int col = cb + tx * 4 + j;
            float ar = accr[i][j], ai = acci[i][j];
            out[(size_t)row * NV + col] = __logf(ar * ar + ai * ai + 1e-12f);
        }
    }
}

// ---------------------------------------------------------------------------
// Row-wise logsumexp, subtract in place.
// ---------------------------------------------------------------------------
__global__ __launch_bounds__(256) void lse_kernel(float* __restrict__ out)
{
    int b = blockIdx.x, tid = threadIdx.x;
    __shared__ float red[8];
    float* row = out + (size_t)b * NV;

    float mx = -INFINITY;
    for (int v = tid; v < NV; v += 256) mx = fmaxf(mx, row[v]);
    for (int o = 16; o; o >>= 1) mx = fmaxf(mx, __shfl_xor_sync(0xffffffffu, mx, o));
    if ((tid & 31) == 0) red[tid >> 5] = mx;
    __syncthreads();
    if (tid < 8) {
        float v = red[tid];
        for (int o = 4; o; o >>= 1) v = fmaxf(v, __shfl_xor_sync(0xffu, v, o));
        if (tid == 0) red[0] = v;
    }
    __syncthreads();
    mx = red[0];
    __syncthreads();

    float se = 0.f;
    for (int v = tid; v < NV; v += 256) se += __expf(row[v] - mx);
    for (int o = 16; o; o >>= 1) se += __shfl_xor_sync(0xffffffffu, se, o);
    if ((tid & 31) == 0) red[tid >> 5] = se;
    __syncthreads();
    if (tid < 8) {
        float v = red[tid];
        for (int o = 4; o; o >>= 1) v += __shfl_xor_sync(0xffu, v, o);
        if (tid == 0) red[0] = v;
    }
    __syncthreads();
    float lse = mx + __logf(red[0]);
    for (int v = tid; v < NV; v += 256) row[v] -= lse;
}

// ---------------------------------------------------------------------------
extern "C" void kernel_launch(void* const* d_in, const int* in_sizes, int n_in,
                              void* d_out, int out_size)
{
    const int*   tokens = (const int*)d_in[0];
    const float* embed  = (const float*)d_in[1];
    const float* W_ih   = (const float*)d_in[2];
    const float* W_hh   = (const float*)d_in[3];
    const float* b_ih   = (const float*)d_in[4];
    const float* b_hh   = (const float*)d_in[5];
    const float* Wc     = (const float*)d_in[6];
    const float* bc     = (const float*)d_in[7];
    const float* phase  = (const float*)d_in[8];
    const float* te     = (const float*)d_in[9];
    const float* pe     = (const float*)d_in[10];
    const float* re_    = (const float*)d_in[11];
    const float* to     = (const float*)d_in[12];
    const float* po     = (const float*)d_in[13];
    const float* ro     = (const float*)d_in[14];
    const float* Rr     = (const float*)d_in[15];
    const float* Ri     = (const float*)d_in[16];
    float* out = (float*)d_out;

    static float* pG = nullptr;
    static float* pH = nullptr;
    static float* pZC = nullptr;
    if (!pG) {
        cudaGetSymbolAddress((void**)&pG, g_G);
        cudaGetSymbolAddress((void**)&pH, g_h);
        cudaGetSymbolAddress((void**)&pZC, g_zc);
        cudaFuncSetAttribute(gru_persist,
                             cudaFuncAttributeMaxDynamicSharedMemorySize, SMEM_BYTES);
    }
    float* pH0 = pH;
    float* pH1 = pH + NB * NE;

    // 1. Token gate table: G = embed @ W_ih^T + b_ih  (V x 3E)
    gemm128_abT<<<dim3(G3E / 64, NV / 128), 256>>>(embed, W_ih, b_ih, pG, G3E, NE);

    // 2. h0 = 0 + barrier state reset
    init_kernel<<<(NB * NE + 255) / 256, 256>>>(pH0);

    // 3. Whole GRU recurrence in ONE persistent kernel (fp16 mma, 4 syncs)
    gru_persist<<<dim3(16, 8), 512, SMEM_BYTES>>>(pH0, pH1, W_hh, b_hh, tokens);

    // 4. zc = h @ Wc^T + bc, then normalized complex psi (NT even -> h in pH0)
    gemm128_abT<<<dim3(2 * NM / 64, NB / 128), 256>>>(pH0, Wc, bc, pZC, 2 * NM, NE);
    psi_init_kernel<<<NB, 256>>>();

    // 5. 32 MZI layers, persistent row in SMEM
    mzi_kernel<<<NB, 512>>>(phase, te, pe, re_, to, po, ro);

    // 6. Readout complex GEMM + log|.|^2, then row logsumexp
    readout_kernel<<<dim3(NV / 64, NB / 64), 256>>>(Rr, Ri, out);
    lse_kernel<<<NB, 256>>>(out);
}

// round 16
// speedup vs baseline: 1.8565x; 1.0254x over previous
#include <cuda_runtime.h>
#include <cuda_fp16.h>
#include <math.h>
#include <string.h>

// Problem dims
#define NB 1024   // batch
#define NT 64     // time steps
#define NV 1024   // vocab
#define NE 512    // embed dim
#define NM 1024   // modes
#define NL 32     // MZI layers
#define NPE 512   // even pairs
#define NPO 511   // odd pairs
#define G3E 1536  // 3*NE

// Scratch (no allocations allowed -> __device__ globals)
__device__ float g_G[NV * G3E];       // token gate table: embed@W_ih^T + b_ih
__device__ float g_h[2][NB * NE];     // GRU hidden double buffer
__device__ float g_zc[NB * 2 * NM];   // h@Wc^T + bc
__device__ float g_pr[NB * NM];       // psi real
__device__ float g_pi[NB * NM];       // psi imag
__device__ unsigned g_barCount[8];    // per-band barrier state
__device__ unsigned g_barGen[8];

// ---------------------------------------------------------------------------
// fp16 helpers
// ---------------------------------------------------------------------------
__device__ __forceinline__ unsigned h2u(__half2 h) {
    unsigned u;
    memcpy(&u, &h, 4);
    return u;
}

__device__ __forceinline__ void mma_f16(float* c, const unsigned* a, const unsigned* b) {
    asm("mma.sync.aligned.m16n8k16.row.col.f32.f16.f16.f32 "
        "{%0,%1,%2,%3}, {%4,%5,%6,%7}, {%8,%9}, {%0,%1,%2,%3};"
        : "+f"(c[0]), "+f"(c[1]), "+f"(c[2]), "+f"(c[3])
        : "r"(a[0]), "r"(a[1]), "r"(a[2]), "r"(a[3]), "r"(b[0]), "r"(b[1]));
}

__device__ __forceinline__ float fast_sigmoid(float x) {
    return 1.f / (1.f + __expf(-x));
}
__device__ __forceinline__ float fast_tanh(float x) {
    x = fminf(15.f, fmaxf(-15.f, x));
    float e2 = __expf(2.f * x);
    return (e2 - 1.f) / (e2 + 1.f);
}

// ---------------------------------------------------------------------------
// Per-band grid barrier: the GRU recurrence only couples the 16 CTAs that
// share blockIdx.y. All 128 CTAs are wave-1 resident (1 CTA/SM).
// ---------------------------------------------------------------------------
#define NCTA_BAND 16
__device__ __forceinline__ void band_sync(int band)
{
    __threadfence();
    __syncthreads();
    if (threadIdx.x == 0) {
        unsigned gen = *(volatile unsigned*)&g_barGen[band];
        if (atomicAdd(&g_barCount[band], 1u) == NCTA_BAND - 1) {
            g_barCount[band] = 0;
            __threadfence();
            atomicExch(&g_barGen[band], gen + 1u);
        } else {
            while (*(volatile unsigned*)&g_barGen[band] == gen) { __nanosleep(32); }
            __threadfence();
        }
    }
    __syncthreads();
}

// ---------------------------------------------------------------------------
// Persistent GRU, fp16 m16n8k16, 512 threads (16 warps), K-split by k16-tile
// parity. Wide 128-col A stages -> only 4 mainloop syncs per step.
// (Unchanged from the R14 best-passing version.)
// ---------------------------------------------------------------------------
#define WS_HALVES (12 * 32 * 32 * 4)    // 49152 halves = 98304 B
#define AS_STRIDE 136                   // halves per row
#define AS_STAGE_H (128 * AS_STRIDE)    // 17408 halves = 34816 B
#define SMEM_BYTES (WS_HALVES * 2 + 2 * AS_STAGE_H * 2)  // 167,936 B

__global__ __launch_bounds__(512, 1) void gru_persist(
    float* __restrict__ h0, float* __restrict__ h1,
    const float* __restrict__ W_hh, const float* __restrict__ b_hh,
    const int* __restrict__ tokens)
{
    extern __shared__ __align__(16) char smem8[];
    __half* Ws = (__half*)smem8;                       // frag-ordered W (fp16)
    __half* As = (__half*)(smem8 + WS_HALVES * 2);     // [2][128][136] halves
    float*  Cs = (float*)(smem8 + WS_HALVES * 2);      // epilogue staging

    int tid = threadIdx.x;
    int lane = tid & 31, w = tid >> 5;   // 16 warps
    int g = lane >> 2, tq = lane & 3;
    int kg = w >> 3;                     // tile parity handled by this warp
    int wl = w & 7;
    int m0w = wl >> 1;                   // warp m-band (0..3)
    int m0 = m0w * 32;
    int n0 = (wl & 1) * 48;              // warp col base (0 or 48)
    int n8base = (wl & 1) * 6;
    int rb = blockIdx.y * 128;           // global row base
    int ecb = blockIdx.x * 32;           // global e base
    int cb = ecb * 3;                    // global gate-col base
    int band = blockIdx.y;

    // ---- one-time: build frag-ordered, gate-interleaved fp16 W slice ----
    for (int idx = tid; idx < 96 * 512; idx += 512) {
        int nl = idx >> 9;               // 0..95
        int k = idx & 511;
        int col = cb + nl;               // interleaved gate col
        int e = col / 3, gg = col - 3 * e;
        __half v = __float2half(W_hh[(size_t)(gg * NE + e) * NE + k]);
        int n8 = nl >> 3, bg = nl & 7;
        int kt = k >> 4, kk = k & 15;
        int btq = (kk >> 1) & 3, reg = kk >> 3, hsel = kk & 1;
        Ws[(((n8 * 32 + kt) * 32 + 4 * bg + btq) << 2) + reg * 2 + hsel] = v;
    }
    __syncthreads();

    // A producer: thread (row = tid>>2, cq = tid&3); per 128-col stage loads
    // 8 float4 at cols 16j + 4cq, stores as half2-pairs (uint2 = 4 halves).
    int aRow = tid >> 2, cq = tid & 3;
    const size_t aRowOff = (size_t)aRow * NE;
    int sBase = aRow * AS_STRIDE + 4 * cq;   // halves

    for (int t = 0; t < NT; t++) {
        const float* hin = (t & 1) ? h1 : h0;
        float* hout      = (t & 1) ? h0 : h1;
        const float* Ag = hin + (size_t)rb * NE;

        // preload stage 0 (cols 0..127)
        {
#pragma unroll
            for (int j = 0; j < 8; j++) {
                float4 a = *(const float4*)(Ag + aRowOff + 16 * j + 4 * cq);
                uint2 u = make_uint2(h2u(__floats2half2_rn(a.x, a.y)),
                                     h2u(__floats2half2_rn(a.z, a.w)));
                *(uint2*)(As + sBase + 16 * j) = u;
            }
        }
        __syncthreads();

        float acc[2][6][4];
#pragma unroll
        for (int mi = 0; mi < 2; mi++)
#pragma unroll
            for (int ni = 0; ni < 6; ni++)
#pragma unroll
                for (int j = 0; j < 4; j++) acc[mi][ni][j] = 0.f;

        for (int ot = 0; ot < 4; ot++) {
            const __half* Acur = As + (ot & 1) * AS_STAGE_H;
            uint2 pre[8];
            if (ot < 3) {
                int c0 = (ot + 1) * 128;
#pragma unroll
                for (int j = 0; j < 8; j++) {
                    float4 a = *(const float4*)(Ag + aRowOff + c0 + 16 * j + 4 * cq);
                    pre[j] = make_uint2(h2u(__floats2half2_rn(a.x, a.y)),
                                        h2u(__floats2half2_rn(a.z, a.w)));
                }
            }
#pragma unroll
            for (int j2 = 0; j2 < 4; j2++) {
                int tl = 2 * j2 + kg;            // tile within stage (0..7)
                int kt = 8 * ot + tl;            // global k16 tile
                unsigned af[2][4];
#pragma unroll
                for (int mi = 0; mi < 2; mi++) {
                    const __half* ap = Acur + (m0 + 16 * mi + g) * AS_STRIDE + 16 * tl + 2 * tq;
                    af[mi][0] = *(const unsigned*)(ap);
                    af[mi][1] = *(const unsigned*)(ap + 8 * AS_STRIDE);
                    af[mi][2] = *(const unsigned*)(ap + 8);
                    af[mi][3] = *(const unsigned*)(ap + 8 * AS_STRIDE + 8);
                }
#pragma unroll
                for (int ni = 0; ni < 6; ni++) {
                    uint2 bv = *(const uint2*)(Ws + ((((n8base + ni) * 32 + kt) * 32 + lane) << 2));
                    unsigned bf[2] = { bv.x, bv.y };
                    mma_f16(acc[0][ni], af[0], bf);
                    mma_f16(acc[1][ni], af[1], bf);
                }
            }
            if (ot < 3) {
                __half* Anxt = As + ((ot + 1) & 1) * AS_STAGE_H;
#pragma unroll
                for (int j = 0; j < 8; j++)
                    *(uint2*)(Anxt + sBase + 16 * j) = pre[j];
            }
            __syncthreads();
        }

        // ---- epilogue: 4 phases of 32 rows; kg0 stores, kg1 adds, gates ----
#pragma unroll
        for (int p = 0; p < 4; p++) {
            if (m0w == p && kg == 0) {
#pragma unroll
                for (int mi = 0; mi < 2; mi++)
#pragma unroll
                    for (int ni = 0; ni < 6; ni++) {
                        int col = n0 + 8 * ni + 2 * tq;
                        *(float2*)&Cs[(16 * mi + g) * 104 + col] =
                            make_float2(acc[mi][ni][0], acc[mi][ni][1]);
                        *(float2*)&Cs[(16 * mi + g + 8) * 104 + col] =
                            make_float2(acc[mi][ni][2], acc[mi][ni][3]);
                    }
            }
            __syncthreads();
            if (m0w == p && kg == 1) {
#pragma unroll
                for (int mi = 0; mi < 2; mi++)
#pragma unroll
                    for (int ni = 0; ni < 6; ni++) {
                        int col = n0 + 8 * ni + 2 * tq;
                        float2* c0 = (float2*)&Cs[(16 * mi + g) * 104 + col];
                        float2 v0 = *c0;
                        v0.x += acc[mi][ni][0]; v0.y += acc[mi][ni][1];
                        *c0 = v0;
                        float2* c1 = (float2*)&Cs[(16 * mi + g + 8) * 104 + col];
                        float2 v1 = *c1;
                        v1.x += acc[mi][ni][2]; v1.y += acc[mi][ni][3];
                        *c1 = v1;
                    }
            }
            __syncthreads();

            for (int i = tid; i < 32 * 32; i += 512) {
                int e = i & 31, r = i >> 5;
                int rg = rb + p * 32 + r;
                int eg = ecb + e;
                float hr = Cs[r * 104 + 3 * e]     + b_hh[eg];
                float hz = Cs[r * 104 + 3 * e + 1] + b_hh[NE + eg];
                float hn = Cs[r * 104 + 3 * e + 2] + b_hh[2 * NE + eg];
                int tok = tokens[rg * NT + t];
                const float* Gr = g_G + (size_t)tok * G3E;
                float ir = Gr[eg], iz = Gr[NE + eg], inn = Gr[2 * NE + eg];
                float rr = fast_sigmoid(ir + hr);
                float zz = fast_sigmoid(iz + hz);
                float nn = fast_tanh(inn + rr * hn);
                float hp = hin[(size_t)rg * NE + eg];
                hout[(size_t)rg * NE + eg] = (1.f - zz) * nn + zz * hp;
            }
            __syncthreads();
        }

        band_sync(band);
    }
}

// ---------------------------------------------------------------------------
// Tiled GEMM: C[Mr x Nc] = A[Mr x K] * Bm[Nc x K]^T + bias[Nc]
// BM=128, BN=64, BK=16, 256 threads, 8x4 microtile.
// ---------------------------------------------------------------------------
__global__ __launch_bounds__(256) void gemm128_abT(
    const float* __restrict__ A, const float* __restrict__ Bm,
    const float* __restrict__ bias, float* __restrict__ C, int Nc, int K)
{
    __shared__ float As[128][17];
    __shared__ float Bs[16][65];
    int tid = threadIdx.x;
    int q = tid & 3;
    int aRow0 = tid >> 2, aRow1 = 64 + (tid >> 2);
    int ty = tid >> 4, tx = tid & 15;
    int rb = blockIdx.y * 128, cbx = blockIdx.x * 64;

    float acc[8][4];
#pragma unroll
    for (int i = 0; i < 8; i++)
#pragma unroll
        for (int j = 0; j < 4; j++) acc[i][j] = 0.f;

    for (int k0 = 0; k0 < K; k0 += 16) {
        float4 av0 = *(const float4*)(A + (size_t)(rb + aRow0) * K + k0 + q * 4);
        float4 av1 = *(const float4*)(A + (size_t)(rb + aRow1) * K + k0 + q * 4);
        As[aRow0][q * 4 + 0] = av0.x; As[aRow0][q * 4 + 1] = av0.y;
        As[aRow0][q * 4 + 2] = av0.z; As[aRow0][q * 4 + 3] = av0.w;
        As[aRow1][q * 4 + 0] = av1.x; As[aRow1][q * 4 + 1] = av1.y;
        As[aRow1][q * 4 + 2] = av1.z; As[aRow1][q * 4 + 3] = av1.w;
        float4 bv = *(const float4*)(Bm + (size_t)(cbx + aRow0) * K + k0 + q * 4);
        Bs[q * 4 + 0][aRow0] = bv.x; Bs[q * 4 + 1][aRow0] = bv.y;
        Bs[q * 4 + 2][aRow0] = bv.z; Bs[q * 4 + 3][aRow0] = bv.w;
        __syncthreads();
#pragma unroll
        for (int kk = 0; kk < 16; kk++) {
            float a[8], b[4];
#pragma unroll
            for (int i = 0; i < 8; i++) a[i] = As[ty * 8 + i][kk];
#pragma unroll
            for (int j = 0; j < 4; j++) b[j] = Bs[kk][tx * 4 + j];
#pragma unroll
            for (int i = 0; i < 8; i++)
#pragma unroll
                for (int j = 0; j < 4; j++) acc[i][j] = fmaf(a[i], b[j], acc[i][j]);
        }
        __syncthreads();
    }
#pragma unroll
    for (int i = 0; i < 8; i++) {
        int row = rb + ty * 8 + i;
#pragma unroll
        for (int j = 0; j < 4; j++) {
            int col = cbx + tx * 4 + j;
            C[(size_t)row * Nc + col] = acc[i][j] + bias[col];
        }
    }
}

__global__ void init_kernel(float* h0)
{
    int i = blockIdx.x * blockDim.x + threadIdx.x;
    if (i < NB * NE) h0[i] = 0.f;
    if (i < 8) { g_barCount[i] = 0u; g_barGen[i] = 0u; }
}

// ---------------------------------------------------------------------------
// psi init: split zc -> (re, im), complex_normalize per row.
// ---------------------------------------------------------------------------
__global__ __launch_bounds__(256) void psi_init_kernel()
{
    int b = blockIdx.x, tid = threadIdx.x;
    __shared__ float red[8];
    const float* zrow = g_zc + (size_t)b * 2 * NM;
    float ss = 0.f;
    for (int m = tid; m < NM; m += 256) {
        float re = zrow[m], im = zrow[NM + m];
        ss += re * re + im * im;
    }
    for (int o = 16; o; o >>= 1) ss += __shfl_xor_sync(0xffffffffu, ss, o);
    if ((tid & 31) == 0) red[tid >> 5] = ss;
    __syncthreads();
    if (tid < 8) {
        float v = red[tid];
        for (int o = 4; o; o >>= 1) v += __shfl_xor_sync(0xffu, v, o);
        if (tid == 0) red[0] = v;
    }
    __syncthreads();
    float inv = rsqrtf(red[0] + 1e-8f);
    for (int m = tid; m < NM; m += 256) {
        g_pr[(size_t)b * NM + m] = zrow[m] * inv;
        g_pi[(size_t)b * NM + m] = zrow[NM + m] * inv;
    }
}

// ---------------------------------------------------------------------------
// MZI layers. Each 2x2 MZI matrix is exactly unitary (rows unit-norm and
// orthogonal), so the reference's per-layer complex_normalize is a no-op up
// to O(eps); furthermore the final logsumexp is invariant to overall row
// scale. We therefore drop the 32 per-layer normalizations (one final
// normalize for magnitude hygiene) and fuse the phase rotation into the
// even-pair step (even pairs partition all modes). 2 syncs/layer.
// ---------------------------------------------------------------------------
__device__ __forceinline__ void pair_apply(int a, int c, float tt, float pp, float rr,
                                           float* sre, float* sim)
{
    float st, ct; __sincosf(tt, &st, &ct);
    float sp, cp; __sincosf(pp, &sp, &cp);
    float sr, cr; __sincosf(rr, &sr, &cr);
    float cpr = cp * cr - sp * sr;
    float spr = sp * cr + cp * sr;
    float u11r = ct * cpr, u11i = ct * spr;
    float u12r = -st * sp, u12i = st * cp;
    float u21r = -st * sr, u21i = st * cr;
    float u22  = ct;
    float v0r = sre[a], v0i = sim[a], v1r = sre[c], v1i = sim[c];
    float n0r = u11r * v0r - u11i * v0i + u12r * v1r - u12i * v1i;
    float n0i = u11r * v0i + u11i * v0r + u12r * v1i + u12i * v1r;
    float n1r = u21r * v0r - u21i * v0i + u22 * v1r;
    float n1i = u21r * v0i + u21i * v0r + u22 * v1i;
    sre[a] = n0r; sim[a] = n0i; sre[c] = n1r; sim[c] = n1i;
}

__global__ __launch_bounds__(512) void mzi_kernel(
    const float* __restrict__ phase, const float* __restrict__ te,
    const float* __restrict__ pe, const float* __restrict__ re_,
    const float* __restrict__ to, const float* __restrict__ po,
    const float* __restrict__ ro)
{
    __shared__ float sre[NM], sim[NM];
    __shared__ float red[16];
    int b = blockIdx.x, tid = threadIdx.x;
    sre[tid] = g_pr[(size_t)b * NM + tid];
    sre[tid + 512] = g_pr[(size_t)b * NM + tid + 512];
    sim[tid] = g_pi[(size_t)b * NM + tid];
    sim[tid + 512] = g_pi[(size_t)b * NM + tid + 512];
    __syncthreads();

    for (int l = 0; l < NL; l++) {
        // fused: phase rotation + even pair (2t, 2t+1)
        {
            int a = 2 * tid, c = a + 1;
            float s0, c0; __sincosf(phase[l * NM + a], &s0, &c0);
            float s1, c1; __sincosf(phase[l * NM + c], &s1, &c1);
            float w0r = sre[a], w0i = sim[a], w1r = sre[c], w1i = sim[c];
            float v0r = w0r * c0 - w0i * s0, v0i = w0r * s0 + w0i * c0;
            float v1r = w1r * c1 - w1i * s1, v1i = w1r * s1 + w1i * c1;
            float st, ct; __sincosf(te[l * NPE + tid], &st, &ct);
            float sp, cp; __sincosf(pe[l * NPE + tid], &sp, &cp);
            float sr, cr; __sincosf(re_[l * NPE + tid], &sr, &cr);
            float cpr = cp * cr - sp * sr;
            float spr = sp * cr + cp * sr;
            float u11r = ct * cpr, u11i = ct * spr;
            float u12r = -st * sp, u12i = st * cp;
            float u21r = -st * sr, u21i = st * cr;
            float u22  = ct;
            sre[a] = u11r * v0r - u11i * v0i + u12r * v1r - u12i * v1i;
            sim[a] = u11r * v0i + u11i * v0r + u12r * v1i + u12i * v1r;
            sre[c] = u21r * v0r - u21i * v0i + u22 * v1r;
            sim[c] = u21r * v0i + u21i * v0r + u22 * v1i;
        }
        __syncthreads();
        // odd pairs (2t+1, 2t+2)
        if (tid < NPO)
            pair_apply(2 * tid + 1, 2 * tid + 2,
                       to[l * NPO + tid], po[l * NPO + tid], ro[l * NPO + tid], sre, sim);
        __syncthreads();
    }

    // single final normalize
    float ss = sre[tid] * sre[tid] + sim[tid] * sim[tid]
             + sre[tid + 512] * sre[tid + 512] + sim[tid + 512] * sim[tid + 512];
    for (int o = 16; o; o >>= 1) ss += __shfl_xor_sync(0xffffffffu, ss, o);
    if ((tid & 31) == 0) red[tid >> 5] = ss;
    __syncthreads();
    if (tid < 16) {
        float v = red[tid];
        for (int o = 8; o; o >>= 1) v += __shfl_xor_sync(0xffffu, v, o);
        if (tid == 0) red[0] = v;
    }
    __syncthreads();
    float inv = rsqrtf(red[0] + 1e-8f);

    g_pr[(size_t)b * NM + tid] = sre[tid] * inv;
    g_pr[(size_t)b * NM + tid + 512] = sre[tid + 512] * inv;
    g_pi[(size_t)b * NM + tid] = sim[tid] * inv;
    g_pi[(size_t)b * NM + tid + 512] = sim[tid + 512] * inv;
}

// ---------------------------------------------------------------------------
// Readout: amps = psi @ R^T (complex), out = log(|amps|^2 + 1e-12).
// 128x64 tiles, 256 threads, 8x4 complex microtile (128 FMA / 24 LDS per kk).
// ---------------------------------------------------------------------------
__global__ __launch_bounds__(256) void readout_kernel(
    const float* __restrict__ Rr, const float* __restrict__ Ri,
    float* __restrict__ out)
{
    __shared__ float Ar[128][17], Ai[128][17];
    __shared__ float Br[16][65], Bi[16][65];
    int tid = threadIdx.x;
    int q = tid & 3;
    int r0 = tid >> 2, r1 = 64 + r0;
    int ty = tid >> 4, tx = tid & 15;
    int rb = blockIdx.y * 128, cbx = blockIdx.x * 64;

    float accr[8][4], acci[8][4];
#pragma unroll
    for (int i = 0; i < 8; i++)
#pragma unroll
        for (int j = 0; j < 4; j++) { accr[i][j] = 0.f; acci[i][j] = 0.f; }

    for (int k0 = 0; k0 < NM; k0 += 16) {
        float4 v;
        v = *(const float4*)(g_pr + (size_t)(rb + r0) * NM + k0 + q * 4);
        Ar[r0][q * 4 + 0] = v.x; Ar[r0][q * 4 + 1] = v.y;
        Ar[r0][q * 4 + 2] = v.z; Ar[r0][q * 4 + 3] = v.w;
        v = *(const float4*)(g_pr + (size_t)(rb + r1) * NM + k0 + q * 4);
        Ar[r1][q * 4 + 0] = v.x; Ar[r1][q * 4 + 1] = v.y;
        Ar[r1][q * 4 + 2] = v.z; Ar[r1][q * 4 + 3] = v.w;
        v = *(const float4*)(g_pi + (size_t)(rb + r0) * NM + k0 + q * 4);
        Ai[r0][q * 4 + 0] = v.x; Ai[r0][q * 4 + 1] = v.y;
        Ai[r0][q * 4 + 2] = v.z; Ai[r0][q * 4 + 3] = v.w;
        v = *(const float4*)(g_pi + (size_t)(rb + r1) * NM + k0 + q * 4);
        Ai[r1][q * 4 + 0] = v.x; Ai[r1][q * 4 + 1] = v.y;
        Ai[r1][q * 4 + 2] = v.z; Ai[r1][q * 4 + 3] = v.w;
        v = *(const float4*)(Rr + (size_t)(cbx + r0) * NM + k0 + q * 4);
        Br[q * 4 + 0][r0] = v.x; Br[q * 4 + 1][r0] = v.y;
        Br[q * 4 + 2][r0] = v.z; Br[q * 4 + 3][r0] = v.w;
        v = *(const float4*)(Ri + (size_t)(cbx + r0) * NM + k0 + q * 4);
        Bi[q * 4 + 0][r0] = v.x; Bi[q * 4 + 1][r0] = v.y;
        Bi[q * 4 + 2][r0] = v.z; Bi[q * 4 + 3][r0] = v.w;
        __syncthreads();
#pragma unroll
        for (int kk = 0; kk < 16; kk++) {
            float par[8], pai[8], wbr[4], wbi[4];
#pragma unroll
            for (int i = 0; i < 8; i++) { par[i] = Ar[ty * 8 + i][kk]; pai[i] = Ai[ty * 8 + i][kk]; }
#pragma unroll
            for (int j = 0; j < 4; j++) { wbr[j] = Br[kk][tx * 4 + j]; wbi[j] = Bi[kk][tx * 4 + j]; }
#pragma unroll
            for (int i = 0; i < 8; i++)
#pragma unroll
                for (int j = 0; j < 4; j++) {
                    accr[i][j] = fmaf(par[i], wbr[j], accr[i][j]);
                    accr[i][j] = fmaf(-pai[i], wbi[j], accr[i][j]);
                    acci[i][j] = fmaf(par[i], wbi[j], acci[i][j]);
                    acci[i][j] = fmaf(pai[i], wbr[j], acci[i][j]);
                }
        }
        __syncthreads();
    }
#pragma unroll
    for (int i = 0; i < 8; i++) {
        int row = rb + ty * 8 + i;
#pragma unroll
        for (int j = 0; j < 4; j++) {
            int col = cbx + tx * 4 + j;
            float ar = accr[i][j], ai = acci[i][j];
            out[(size_t)row * NV + col] = __logf(ar * ar + ai * ai + 1e-12f);
        }
    }
}

// ---------------------------------------------------------------------------
// Row-wise logsumexp, subtract in place.
// ---------------------------------------------------------------------------
__global__ __launch_bounds__(256) void lse_kernel(float* __restrict__ out)
{
    int b = blockIdx.x, tid = threadIdx.x;
    __shared__ float red[8];
    float* row = out + (size_t)b * NV;

    float mx = -INFINITY;
    for (int v = tid; v < NV; v += 256) mx = fmaxf(mx, row[v]);
    for (int o = 16; o; o >>= 1) mx = fmaxf(mx, __shfl_xor_sync(0xffffffffu, mx, o));
    if ((tid & 31) == 0) red[tid >> 5] = mx;
    __syncthreads();
    if (tid < 8) {
        float v = red[tid];
        for (int o = 4; o; o >>= 1) v = fmaxf(v, __shfl_xor_sync(0xffu, v, o));
        if (tid == 0) red[0] = v;
    }
    __syncthreads();
    mx = red[0];
    __syncthreads();

    float se = 0.f;
    for (int v = tid; v < NV; v += 256) se += __expf(row[v] - mx);
    for (int o = 16; o; o >>= 1) se += __shfl_xor_sync(0xffffffffu, se, o);
    if ((tid & 31) == 0) red[tid >> 5] = se;
    __syncthreads();
    if (tid < 8) {
        float v = red[tid];
        for (int o = 4; o; o >>= 1) v += __shfl_xor_sync(0xffu, v, o);
        if (tid == 0) red[0] = v;
    }
    __syncthreads();
    float lse = mx + __logf(red[0]);
    for (int v = tid; v < NV; v += 256) row[v] -= lse;
}

// ---------------------------------------------------------------------------
extern "C" void kernel_launch(void* const* d_in, const int* in_sizes, int n_in,
                              void* d_out, int out_size)
{
    const int*   tokens = (const int*)d_in[0];
    const float* embed  = (const float*)d_in[1];
    const float* W_ih   = (const float*)d_in[2];
    const float* W_hh   = (const float*)d_in[3];
    const float* b_ih   = (const float*)d_in[4];
    const float* b_hh   = (const float*)d_in[5];
    const float* Wc     = (const float*)d_in[6];
    const float* bc     = (const float*)d_in[7];
    const float* phase  = (const float*)d_in[8];
    const float* te     = (const float*)d_in[9];
    const float* pe     = (const float*)d_in[10];
    const float* re_    = (const float*)d_in[11];
    const float* to     = (const float*)d_in[12];
    const float* po     = (const float*)d_in[13];
    const float* ro     = (const float*)d_in[14];
    const float* Rr     = (const float*)d_in[15];
    const float* Ri     = (const float*)d_in[16];
    float* out = (float*)d_out;

    static float* pG = nullptr;
    static float* pH = nullptr;
    static float* pZC = nullptr;
    if (!pG) {
        cudaGetSymbolAddress((void**)&pG, g_G);
        cudaGetSymbolAddress((void**)&pH, g_h);
        cudaGetSymbolAddress((void**)&pZC, g_zc);
        cudaFuncSetAttribute(gru_persist,
                             cudaFuncAttributeMaxDynamicSharedMemorySize, SMEM_BYTES);
    }
    float* pH0 = pH;
    float* pH1 = pH + NB * NE;

    // 1. Token gate table: G = embed @ W_ih^T + b_ih  (V x 3E)
    gemm128_abT<<<dim3(G3E / 64, NV / 128), 256>>>(embed, W_ih, b_ih, pG, G3E, NE);

    // 2. h0 = 0 + barrier state reset
    init_kernel<<<(NB * NE + 255) / 256, 256>>>(pH0);

    // 3. Whole GRU recurrence in ONE persistent kernel (fp16 mma, 4 syncs)
    gru_persist<<<dim3(16, 8), 512, SMEM_BYTES>>>(pH0, pH1, W_hh, b_hh, tokens);

    // 4. zc = h @ Wc^T + bc, then normalized complex psi (NT even -> h in pH0)
    gemm128_abT<<<dim3(2 * NM / 64, NB / 128), 256>>>(pH0, Wc, bc, pZC, 2 * NM, NE);
    psi_init_kernel<<<NB, 256>>>();

    // 5. 32 MZI layers (unitary -> per-layer norms dropped, phase fused)
    mzi_kernel<<<NB, 512>>>(phase, te, pe, re_, to, po, ro);

    // 6. Readout complex GEMM + log|.|^2, then row logsumexp
    readout_kernel<<<dim3(NV / 64, NB / 128), 256>>>(Rr, Ri, out);
    lse_kernel<<<NB, 256>>>(out);
}

// round 17
// speedup vs baseline: 1.9205x; 1.0345x over previous
#include <cuda_runtime.h>
#include <cuda_fp16.h>
#include <math.h>
#include <string.h>

// Problem dims
#define NB 1024   // batch
#define NT 64     // time steps
#define NV 1024   // vocab
#define NE 512    // embed dim
#define NM 1024   // modes
#define NL 32     // MZI layers
#define NPE 512   // even pairs
#define NPO 511   // odd pairs
#define G3E 1536  // 3*NE

// Scratch (no allocations allowed -> __device__ globals)
__device__ float g_G[NV * G3E];       // token gate table: embed@W_ih^T + b_ih
__device__ float g_h[2][NB * NE];     // GRU hidden double buffer (fp32, for hp)
__device__ __half g_hh[2][NB * NE];   // fp16 shadow of h (GEMM operand path)
__device__ float g_zc[NB * 2 * NM];   // h@Wc^T + bc
__device__ float g_pr[NB * NM];       // psi real
__device__ float g_pi[NB * NM];       // psi imag
__device__ unsigned g_barCount[8];    // per-band barrier state
__device__ unsigned g_barGen[8];

// ---------------------------------------------------------------------------
// fp16 helpers
// ---------------------------------------------------------------------------
__device__ __forceinline__ unsigned h2u(__half2 h) {
    unsigned u;
    memcpy(&u, &h, 4);
    return u;
}

__device__ __forceinline__ void mma_f16(float* c, const unsigned* a, const unsigned* b) {
    asm("mma.sync.aligned.m16n8k16.row.col.f32.f16.f16.f32 "
        "{%0,%1,%2,%3}, {%4,%5,%6,%7}, {%8,%9}, {%0,%1,%2,%3};"
        : "+f"(c[0]), "+f"(c[1]), "+f"(c[2]), "+f"(c[3])
        : "r"(a[0]), "r"(a[1]), "r"(a[2]), "r"(a[3]), "r"(b[0]), "r"(b[1]));
}

__device__ __forceinline__ float fast_sigmoid(float x) {
    return 1.f / (1.f + __expf(-x));
}
__device__ __forceinline__ float fast_tanh(float x) {
    x = fminf(15.f, fmaxf(-15.f, x));
    float e2 = __expf(2.f * x);
    return (e2 - 1.f) / (e2 + 1.f);
}

// ---------------------------------------------------------------------------
// Per-band grid barrier: the GRU recurrence only couples the 16 CTAs that
// share blockIdx.y. All 128 CTAs are wave-1 resident (1 CTA/SM).
// ---------------------------------------------------------------------------
#define NCTA_BAND 16
__device__ __forceinline__ void band_sync(int band)
{
    __threadfence();
    __syncthreads();
    if (threadIdx.x == 0) {
        unsigned gen = *(volatile unsigned*)&g_barGen[band];
        if (atomicAdd(&g_barCount[band], 1u) == NCTA_BAND - 1) {
            g_barCount[band] = 0;
            __threadfence();
            atomicExch(&g_barGen[band], gen + 1u);
        } else {
            while (*(volatile unsigned*)&g_barGen[band] == gen) { __nanosleep(32); }
            __threadfence();
        }
    }
    __syncthreads();
}

// ---------------------------------------------------------------------------
// Persistent GRU, fp16 m16n8k16, 512 threads (16 warps), K-split by k16-tile
// parity. Wide 128-col A stages (4 mainloop syncs). A operand sourced from
// the fp16 shadow g_hh (bit-identical to converting the fp32 h, but half the
// LDG bytes and no cvt chains). Single-pass epilogue: full 128x104 f32 C
// staging in the dead A region -> 3 epilogue syncs (was 12).
// ---------------------------------------------------------------------------
#define WS_HALVES (12 * 32 * 32 * 4)    // 49152 halves = 98304 B
#define AS_STRIDE 136                   // halves per row
#define AS_STAGE_H (128 * AS_STRIDE)    // 17408 halves = 34816 B
#define SMEM_BYTES (WS_HALVES * 2 + 2 * AS_STAGE_H * 2)  // 167,936 B
// Cs (128 x 104 f32 = 53,248 B) overlays the 69,632 B A-stage region.

__global__ __launch_bounds__(512, 1) void gru_persist(
    float* __restrict__ h0, float* __restrict__ h1,
    const float* __restrict__ W_hh, const float* __restrict__ b_hh,
    const int* __restrict__ tokens)
{
    extern __shared__ __align__(16) char smem8[];
    __half* Ws = (__half*)smem8;                       // frag-ordered W (fp16)
    __half* As = (__half*)(smem8 + WS_HALVES * 2);     // [2][128][136] halves
    float*  Cs = (float*)(smem8 + WS_HALVES * 2);      // epilogue staging

    int tid = threadIdx.x;
    int lane = tid & 31, w = tid >> 5;   // 16 warps
    int g = lane >> 2, tq = lane & 3;
    int kg = w >> 3;                     // tile parity handled by this warp
    int wl = w & 7;
    int m0w = wl >> 1;                   // warp m-band (0..3)
    int m0 = m0w * 32;
    int n0 = (wl & 1) * 48;              // warp col base (0 or 48)
    int n8base = (wl & 1) * 6;
    int rb = blockIdx.y * 128;           // global row base
    int ecb = blockIdx.x * 32;           // global e base
    int cb = ecb * 3;                    // global gate-col base
    int band = blockIdx.y;

    // ---- one-time: build frag-ordered, gate-interleaved fp16 W slice ----
    for (int idx = tid; idx < 96 * 512; idx += 512) {
        int nl = idx >> 9;               // 0..95
        int k = idx & 511;
        int col = cb + nl;               // interleaved gate col
        int e = col / 3, gg = col - 3 * e;
        __half v = __float2half(W_hh[(size_t)(gg * NE + e) * NE + k]);
        int n8 = nl >> 3, bg = nl & 7;
        int kt = k >> 4, kk = k & 15;
        int btq = (kk >> 1) & 3, reg = kk >> 3, hsel = kk & 1;
        Ws[(((n8 * 32 + kt) * 32 + 4 * bg + btq) << 2) + reg * 2 + hsel] = v;
    }
    __syncthreads();

    // A producer: thread (row = tid>>2, cq = tid&3); per 128-col stage copies
    // 8 uint2 (4 halves each) from the fp16 shadow at cols 16j + 4cq.
    int aRow = tid >> 2, cq = tid & 3;
    const size_t aRowOff = (size_t)aRow * NE;
    int sBase = aRow * AS_STRIDE + 4 * cq;   // halves

    for (int t = 0; t < NT; t++) {
        const float*  hin   = (t & 1) ? h1 : h0;
        float*        hout  = (t & 1) ? h0 : h1;
        const __half* hhin  = g_hh[t & 1];
        __half*       hhout = g_hh[1 - (t & 1)];
        const __half* Agh = hhin + (size_t)rb * NE;

        // preload stage 0 (cols 0..127)
#pragma unroll
        for (int j = 0; j < 8; j++)
            *(uint2*)(As + sBase + 16 * j) =
                *(const uint2*)(Agh + aRowOff + 16 * j + 4 * cq);
        __syncthreads();

        float acc[2][6][4];
#pragma unroll
        for (int mi = 0; mi < 2; mi++)
#pragma unroll
            for (int ni = 0; ni < 6; ni++)
#pragma unroll
                for (int j = 0; j < 4; j++) acc[mi][ni][j] = 0.f;

        for (int ot = 0; ot < 4; ot++) {
            const __half* Acur = As + (ot & 1) * AS_STAGE_H;
            uint2 pre[8];
            if (ot < 3) {
                int c0 = (ot + 1) * 128;
#pragma unroll
                for (int j = 0; j < 8; j++)
                    pre[j] = *(const uint2*)(Agh + aRowOff + c0 + 16 * j + 4 * cq);
            }
#pragma unroll
            for (int j2 = 0; j2 < 4; j2++) {
                int tl = 2 * j2 + kg;            // tile within stage (0..7)
                int kt = 8 * ot + tl;            // global k16 tile
                unsigned af[2][4];
#pragma unroll
                for (int mi = 0; mi < 2; mi++) {
                    const __half* ap = Acur + (m0 + 16 * mi + g) * AS_STRIDE + 16 * tl + 2 * tq;
                    af[mi][0] = *(const unsigned*)(ap);
                    af[mi][1] = *(const unsigned*)(ap + 8 * AS_STRIDE);
                    af[mi][2] = *(const unsigned*)(ap + 8);
                    af[mi][3] = *(const unsigned*)(ap + 8 * AS_STRIDE + 8);
                }
#pragma unroll
                for (int ni = 0; ni < 6; ni++) {
                    uint2 bv = *(const uint2*)(Ws + ((((n8base + ni) * 32 + kt) * 32 + lane) << 2));
                    unsigned bf[2] = { bv.x, bv.y };
                    mma_f16(acc[0][ni], af[0], bf);
                    mma_f16(acc[1][ni], af[1], bf);
                }
            }
            if (ot < 3) {
                __half* Anxt = As + ((ot + 1) & 1) * AS_STAGE_H;
#pragma unroll
                for (int j = 0; j < 8; j++)
                    *(uint2*)(Anxt + sBase + 16 * j) = pre[j];
            }
            __syncthreads();
        }

        // ---- single-pass epilogue: kg0 stores all rows, kg1 adds, gates ----
        if (kg == 0) {
#pragma unroll
            for (int mi = 0; mi < 2; mi++)
#pragma unroll
                for (int ni = 0; ni < 6; ni++) {
                    int col = n0 + 8 * ni + 2 * tq;
                    *(float2*)&Cs[(m0 + 16 * mi + g) * 104 + col] =
                        make_float2(acc[mi][ni][0], acc[mi][ni][1]);
                    *(float2*)&Cs[(m0 + 16 * mi + g + 8) * 104 + col] =
                        make_float2(acc[mi][ni][2], acc[mi][ni][3]);
                }
        }
        __syncthreads();
        if (kg == 1) {
#pragma unroll
            for (int mi = 0; mi < 2; mi++)
#pragma unroll
                for (int ni = 0; ni < 6; ni++) {
                    int col = n0 + 8 * ni + 2 * tq;
                    float2* c0 = (float2*)&Cs[(m0 + 16 * mi + g) * 104 + col];
                    float2 v0 = *c0;
                    v0.x += acc[mi][ni][0]; v0.y += acc[mi][ni][1];
                    *c0 = v0;
                    float2* c1 = (float2*)&Cs[(m0 + 16 * mi + g + 8) * 104 + col];
                    float2 v1 = *c1;
                    v1.x += acc[mi][ni][2]; v1.y += acc[mi][ni][3];
                    *c1 = v1;
                }
        }
        __syncthreads();

        for (int i = tid; i < 128 * 32; i += 512) {
            int e = i & 31, r = i >> 5;
            int rg = rb + r;
            int eg = ecb + e;
            float hr = Cs[r * 104 + 3 * e]     + b_hh[eg];
            float hz = Cs[r * 104 + 3 * e + 1] + b_hh[NE + eg];
            float hn = Cs[r * 104 + 3 * e + 2] + b_hh[2 * NE + eg];
            int tok = tokens[rg * NT + t];
            const float* Gr = g_G + (size_t)tok * G3E;
            float ir = Gr[eg], iz = Gr[NE + eg], inn = Gr[2 * NE + eg];
            float rr = fast_sigmoid(ir + hr);
            float zz = fast_sigmoid(iz + hz);
            float nn = fast_tanh(inn + rr * hn);
            float hp = hin[(size_t)rg * NE + eg];
            float hv = (1.f - zz) * nn + zz * hp;
            hout[(size_t)rg * NE + eg] = hv;
            hhout[(size_t)rg * NE + eg] = __float2half(hv);
        }

        band_sync(band);
    }
}

// ---------------------------------------------------------------------------
// Tiled GEMM: C[Mr x Nc] = A[Mr x K] * Bm[Nc x K]^T + bias[Nc]
// BM=128, BN=64, BK=16, 256 threads, 8x4 microtile.
// ---------------------------------------------------------------------------
__global__ __launch_bounds__(256) void gemm128_abT(
    const float* __restrict__ A, const float* __restrict__ Bm,
    const float* __restrict__ bias, float* __restrict__ C, int Nc, int K)
{
    __shared__ float As[128][17];
    __shared__ float Bs[16][65];
    int tid = threadIdx.x;
    int q = tid & 3;
    int aRow0 = tid >> 2, aRow1 = 64 + (tid >> 2);
    int ty = tid >> 4, tx = tid & 15;
    int rb = blockIdx.y * 128, cbx = blockIdx.x * 64;

    float acc[8][4];
#pragma unroll
    for (int i = 0; i < 8; i++)
#pragma unroll
        for (int j = 0; j < 4; j++) acc[i][j] = 0.f;

    for (int k0 = 0; k0 < K; k0 += 16) {
        float4 av0 = *(const float4*)(A + (size_t)(rb + aRow0) * K + k0 + q * 4);
        float4 av1 = *(const float4*)(A + (size_t)(rb + aRow1) * K + k0 + q * 4);
        As[aRow0][q * 4 + 0] = av0.x; As[aRow0][q * 4 + 1] = av0.y;
        As[aRow0][q * 4 + 2] = av0.z; As[aRow0][q * 4 + 3] = av0.w;
        As[aRow1][q * 4 + 0] = av1.x; As[aRow1][q * 4 + 1] = av1.y;
        As[aRow1][q * 4 + 2] = av1.z; As[aRow1][q * 4 + 3] = av1.w;
        float4 bv = *(const float4*)(Bm + (size_t)(cbx + aRow0) * K + k0 + q * 4);
        Bs[q * 4 + 0][aRow0] = bv.x; Bs[q * 4 + 1][aRow0] = bv.y;
        Bs[q * 4 + 2][aRow0] = bv.z; Bs[q * 4 + 3][aRow0] = bv.w;
        __syncthreads();
#pragma unroll
        for (int kk = 0; kk < 16; kk++) {
            float a[8], b[4];
#pragma unroll
            for (int i = 0; i < 8; i++) a[i] = As[ty * 8 + i][kk];
#pragma unroll
            for (int j = 0; j < 4; j++) b[j] = Bs[kk][tx * 4 + j];
#pragma unroll
            for (int i = 0; i < 8; i++)
#pragma unroll
                for (int j = 0; j < 4; j++) acc[i][j] = fmaf(a[i], b[j], acc[i][j]);
        }
        __syncthreads();
    }
#pragma unroll
    for (int i = 0; i < 8; i++) {
        int row = rb + ty * 8 + i;
#pragma unroll
        for (int j = 0; j < 4; j++) {
            int col = cbx + tx * 4 + j;
            C[(size_t)row * Nc + col] = acc[i][j] + bias[col];
        }
    }
}

__global__ void init_kernel(float* h0)
{
    int i = blockIdx.x * blockDim.x + threadIdx.x;
    if (i < NB * NE) {
        h0[i] = 0.f;
        g_hh[0][i] = __float2half(0.f);
    }
    if (i < 8) { g_barCount[i] = 0u; g_barGen[i] = 0u; }
}

// ---------------------------------------------------------------------------
// psi init: split zc -> (re, im), complex_normalize per row.
// ---------------------------------------------------------------------------
__global__ __launch_bounds__(256) void psi_init_kernel()
{
    int b = blockIdx.x, tid = threadIdx.x;
    __shared__ float red[8];
    const float* zrow = g_zc + (size_t)b * 2 * NM;
    float ss = 0.f;
    for (int m = tid; m < NM; m += 256) {
        float re = zrow[m], im = zrow[NM + m];
        ss += re * re + im * im;
    }
    for (int o = 16; o; o >>= 1) ss += __shfl_xor_sync(0xffffffffu, ss, o);
    if ((tid & 31) == 0) red[tid >> 5] = ss;
    __syncthreads();
    if (tid < 8) {
        float v = red[tid];
        for (int o = 4; o; o >>= 1) v += __shfl_xor_sync(0xffu, v, o);
        if (tid == 0) red[0] = v;
    }
    __syncthreads();
    float inv = rsqrtf(red[0] + 1e-8f);
    for (int m = tid; m < NM; m += 256) {
        g_pr[(size_t)b * NM + m] = zrow[m] * inv;
        g_pi[(size_t)b * NM + m] = zrow[NM + m] * inv;
    }
}

// ---------------------------------------------------------------------------
// MZI layers (unitary -> per-layer norms dropped, phase fused, 2 syncs/layer).
// ---------------------------------------------------------------------------
__device__ __forceinline__ void pair_apply(int a, int c, float tt, float pp, float rr,
                                           float* sre, float* sim)
{
    float st, ct; __sincosf(tt, &st, &ct);
    float sp, cp; __sincosf(pp, &sp, &cp);
    float sr, cr; __sincosf(rr, &sr, &cr);
    float cpr = cp * cr - sp * sr;
    float spr = sp * cr + cp * sr;
    float u11r = ct * cpr, u11i = ct * spr;
    float u12r = -st * sp, u12i = st * cp;
    float u21r = -st * sr, u21i = st * cr;
    float u22  = ct;
    float v0r = sre[a], v0i = sim[a], v1r = sre[c], v1i = sim[c];
    float n0r = u11r * v0r - u11i * v0i + u12r * v1r - u12i * v1i;
    float n0i = u11r * v0i + u11i * v0r + u12r * v1i + u12i * v1r;
    float n1r = u21r * v0r - u21i * v0i + u22 * v1r;
    float n1i = u21r * v0i + u21i * v0r + u22 * v1i;
    sre[a] = n0r; sim[a] = n0i; sre[c] = n1r; sim[c] = n1i;
}

__global__ __launch_bounds__(512) void mzi_kernel(
    const float* __restrict__ phase, const float* __restrict__ te,
    const float* __restrict__ pe, const float* __restrict__ re_,
    const float* __restrict__ to, const float* __restrict__ po,
    const float* __restrict__ ro)
{
    __shared__ float sre[NM], sim[NM];
    __shared__ float red[16];
    int b = blockIdx.x, tid = threadIdx.x;
    sre[tid] = g_pr[(size_t)b * NM + tid];
    sre[tid + 512] = g_pr[(size_t)b * NM + tid + 512];
    sim[tid] = g_pi[(size_t)b * NM + tid];
    sim[tid + 512] = g_pi[(size_t)b * NM + tid + 512];
    __syncthreads();

    for (int l = 0; l < NL; l++) {
        // fused: phase rotation + even pair (2t, 2t+1)
        {
            int a = 2 * tid, c = a + 1;
            float s0, c0; __sincosf(phase[l * NM + a], &s0, &c0);
            float s1, c1; __sincosf(phase[l * NM + c], &s1, &c1);
            float w0r = sre[a], w0i = sim[a], w1r = sre[c], w1i = sim[c];
            float v0r = w0r * c0 - w0i * s0, v0i = w0r * s0 + w0i * c0;
            float v1r = w1r * c1 - w1i * s1, v1i = w1r * s1 + w1i * c1;
            float st, ct; __sincosf(te[l * NPE + tid], &st, &ct);
            float sp, cp; __sincosf(pe[l * NPE + tid], &sp, &cp);
            float sr, cr; __sincosf(re_[l * NPE + tid], &sr, &cr);
            float cpr = cp * cr - sp * sr;
            float spr = sp * cr + cp * sr;
            float u11r = ct * cpr, u11i = ct * spr;
            float u12r = -st * sp, u12i = st * cp;
            float u21r = -st * sr, u21i = st * cr;
            float u22  = ct;
            sre[a] = u11r * v0r - u11i * v0i + u12r * v1r - u12i * v1i;
            sim[a] = u11r * v0i + u11i * v0r + u12r * v1i + u12i * v1r;
            sre[c] = u21r * v0r - u21i * v0i + u22 * v1r;
            sim[c] = u21r * v0i + u21i * v0r + u22 * v1i;
        }
        __syncthreads();
        // odd pairs (2t+1, 2t+2)
        if (tid < NPO)
            pair_apply(2 * tid + 1, 2 * tid + 2,
                       to[l * NPO + tid], po[l * NPO + tid], ro[l * NPO + tid], sre, sim);
        __syncthreads();
    }

    // single final normalize
    float ss = sre[tid] * sre[tid] + sim[tid] * sim[tid]
             + sre[tid + 512] * sre[tid + 512] + sim[tid + 512] * sim[tid + 512];
    for (int o = 16; o; o >>= 1) ss += __shfl_xor_sync(0xffffffffu, ss, o);
    if ((tid & 31) == 0) red[tid >> 5] = ss;
    __syncthreads();
    if (tid < 16) {
        float v = red[tid];
        for (int o = 8; o; o >>= 1) v += __shfl_xor_sync(0xffffu, v, o);
        if (tid == 0) red[0] = v;
    }
    __syncthreads();
    float inv = rsqrtf(red[0] + 1e-8f);

    g_pr[(size_t)b * NM + tid] = sre[tid] * inv;
    g_pr[(size_t)b * NM + tid + 512] = sre[tid + 512] * inv;
    g_pi[(size_t)b * NM + tid] = sim[tid] * inv;
    g_pi[(size_t)b * NM + tid + 512] = sim[tid + 512] * inv;
}

// ---------------------------------------------------------------------------
// Readout: amps = psi @ R^T (complex), out = log(|amps|^2 + 1e-12).
// 128x64 tiles, 256 threads, 8x4 complex microtile.
// ---------------------------------------------------------------------------
__global__ __launch_bounds__(256) void readout_kernel(
    const float* __restrict__ Rr, const float* __restrict__ Ri,
    float* __restrict__ out)
{
    __shared__ float Ar[128][17], Ai[128][17];
    __shared__ float Br[16][65], Bi[16][65];
    int tid = threadIdx.x;
    int q = tid & 3;
    int r0 = tid >> 2, r1 = 64 + r0;
    int ty = tid >> 4, tx = tid & 15;
    int rb = blockIdx.y * 128, cbx = blockIdx.x * 64;

    float accr[8][4], acci[8][4];
#pragma unroll
    for (int i = 0; i < 8; i++)
#pragma unroll
        for (int j = 0; j < 4; j++) { accr[i][j] = 0.f; acci[i][j] = 0.f; }

    for (int k0 = 0; k0 < NM; k0 += 16) {
        float4 v;
        v = *(const float4*)(g_pr + (size_t)(rb + r0) * NM + k0 + q * 4);
        Ar[r0][q * 4 + 0] = v.x; Ar[r0][q * 4 + 1] = v.y;
        Ar[r0][q * 4 + 2] = v.z; Ar[r0][q * 4 + 3] = v.w;
        v = *(const float4*)(g_pr + (size_t)(rb + r1) * NM + k0 + q * 4);
        Ar[r1][q * 4 + 0] = v.x; Ar[r1][q * 4 + 1] = v.y;
        Ar[r1][q * 4 + 2] = v.z; Ar[r1][q * 4 + 3] = v.w;
        v = *(const float4*)(g_pi + (size_t)(rb + r0) * NM + k0 + q * 4);
        Ai[r0][q * 4 + 0] = v.x; Ai[r0][q * 4 + 1] = v.y;
        Ai[r0][q * 4 + 2] = v.z; Ai[r0][q * 4 + 3] = v.w;
        v = *(const float4*)(g_pi + (size_t)(rb + r1) * NM + k0 + q * 4);
        Ai[r1][q * 4 + 0] = v.x; Ai[r1][q * 4 + 1] = v.y;
        Ai[r1][q * 4 + 2] = v.z; Ai[r1][q * 4 + 3] = v.w;
        v = *(const float4*)(Rr + (size_t)(cbx + r0) * NM + k0 + q * 4);
        Br[q * 4 + 0][r0] = v.x; Br[q * 4 + 1][r0] = v.y;
        Br[q * 4 + 2][r0] = v.z; Br[q * 4 + 3][r0] = v.w;
        v = *(const float4*)(Ri + (size_t)(cbx + r0) * NM + k0 + q * 4);
        Bi[q * 4 + 0][r0] = v.x; Bi[q * 4 + 1][r0] = v.y;
        Bi[q * 4 + 2][r0] = v.z; Bi[q * 4 + 3][r0] = v.w;
        __syncthreads();
#pragma unroll
        for (int kk = 0; kk < 16; kk++) {
            float par[8], pai[8], wbr[4], wbi[4];
#pragma unroll
            for (int i = 0; i < 8; i++) { par[i] = Ar[ty * 8 + i][kk]; pai[i] = Ai[ty * 8 + i][kk]; }
#pragma unroll
            for (int j = 0; j < 4; j++) { wbr[j] = Br[kk][tx * 4 + j]; wbi[j] = Bi[kk][tx * 4 + j]; }
#pragma unroll
            for (int i = 0; i < 8; i++)
#pragma unroll
                for (int j = 0; j < 4; j++) {
                    accr[i][j] = fmaf(par[i], wbr[j], accr[i][j]);
                    accr[i][j] = fmaf(-pai[i], wbi[j], accr[i][j]);
                    acci[i][j] = fmaf(par[i], wbi[j], acci[i][j]);
                    acci[i][j] = fmaf(pai[i], wbr[j], acci[i][j]);
                }
        }
        __syncthreads();
    }
#pragma unroll
    for (int i = 0; i < 8; i++) {
        int row = rb + ty * 8 + i;
#pragma unroll
        for (int j = 0; j < 4; j++) {
            int col = cbx + tx * 4 + j;
            float ar = accr[i][j], ai = acci[i][j];
            out[(size_t)row * NV + col] = __logf(ar * ar + ai * ai + 1e-12f);
        }
    }
}

// ---------------------------------------------------------------------------
// Row-wise logsumexp, subtract in place.
// ---------------------------------------------------------------------------
__global__ __launch_bounds__(256) void lse_kernel(float* __restrict__ out)
{
    int b = blockIdx.x, tid = threadIdx.x;
    __shared__ float red[8];
    float* row = out + (size_t)b * NV;

    float mx = -INFINITY;
    for (int v = tid; v < NV; v += 256) mx = fmaxf(mx, row[v]);
    for (int o = 16; o; o >>= 1) mx = fmaxf(mx, __shfl_xor_sync(0xffffffffu, mx, o));
    if ((tid & 31) == 0) red[tid >> 5] = mx;
    __syncthreads();
    if (tid < 8) {
        float v = red[tid];
        for (int o = 4; o; o >>= 1) v = fmaxf(v, __shfl_xor_sync(0xffu, v, o));
        if (tid == 0) red[0] = v;
    }
    __syncthreads();
    mx = red[0];
    __syncthreads();

    float se = 0.f;
    for (int v = tid; v < NV; v += 256) se += __expf(row[v] - mx);
    for (int o = 16; o; o >>= 1) se += __shfl_xor_sync(0xffffffffu, se, o);
    if ((tid & 31) == 0) red[tid >> 5] = se;
    __syncthreads();
    if (tid < 8) {
        float v = red[tid];
        for (int o = 4; o; o >>= 1) v += __shfl_xor_sync(0xffu, v, o);
        if (tid == 0) red[0] = v;
    }
    __syncthreads();
    float lse = mx + __logf(red[0]);
    for (int v = tid; v < NV; v += 256) row[v] -= lse;
}

// ---------------------------------------------------------------------------
extern "C" void kernel_launch(void* const* d_in, const int* in_sizes, int n_in,
                              void* d_out, int out_size)
{
    const int*   tokens = (const int*)d_in[0];
    const float* embed  = (const float*)d_in[1];
    const float* W_ih   = (const float*)d_in[2];
    const float* W_hh   = (const float*)d_in[3];
    const float* b_ih   = (const float*)d_in[4];
    const float* b_hh   = (const float*)d_in[5];
    const float* Wc     = (const float*)d_in[6];
    const float* bc     = (const float*)d_in[7];
    const float* phase  = (const float*)d_in[8];
    const float* te     = (const float*)d_in[9];
    const float* pe     = (const float*)d_in[10];
    const float* re_    = (const float*)d_in[11];
    const float* to     = (const float*)d_in[12];
    const float* po     = (const float*)d_in[13];
    const float* ro     = (const float*)d_in[14];
    const float* Rr     = (const float*)d_in[15];
    const float* Ri     = (const float*)d_in[16];
    float* out = (float*)d_out;

    static float* pG = nullptr;
    static float* pH = nullptr;
    static float* pZC = nullptr;
    if (!pG) {
        cudaGetSymbolAddress((void**)&pG, g_G);
        cudaGetSymbolAddress((void**)&pH, g_h);
        cudaGetSymbolAddress((void**)&pZC, g_zc);
        cudaFuncSetAttribute(gru_persist,
                             cudaFuncAttributeMaxDynamicSharedMemorySize, SMEM_BYTES);
    }
    float* pH0 = pH;
    float* pH1 = pH + NB * NE;

    // 1. Token gate table: G = embed @ W_ih^T + b_ih  (V x 3E)
    gemm128_abT<<<dim3(G3E / 64, NV / 128), 256>>>(embed, W_ih, b_ih, pG, G3E, NE);

    // 2. h0 = 0 (fp32 + fp16 shadow) + barrier state reset
    init_kernel<<<(NB * NE + 255) / 256, 256>>>(pH0);

    // 3. Whole GRU recurrence in ONE persistent kernel (fp16 mma)
    gru_persist<<<dim3(16, 8), 512, SMEM_BYTES>>>(pH0, pH1, W_hh, b_hh, tokens);

    // 4. zc = h @ Wc^T + bc, then normalized complex psi (NT even -> h in pH0)
    gemm128_abT<<<dim3(2 * NM / 64, NB / 128), 256>>>(pH0, Wc, bc, pZC, 2 * NM, NE);
    psi_init_kernel<<<NB, 256>>>();

    // 5. 32 MZI layers (unitary -> per-layer norms dropped, phase fused)
    mzi_kernel<<<NB, 512>>>(phase, te, pe, re_, to, po, ro);

    // 6. Readout complex GEMM + log|.|^2, then row logsumexp
    readout_kernel<<<dim3(NV / 64, NB / 128), 256>>>(Rr, Ri, out);
    lse_kernel<<<NB, 256>>>(out);
}